// round 1
// baseline (speedup 1.0000x reference)
#include <cuda_runtime.h>

// ---------------------------------------------------------------------------
// Problem constants
// ---------------------------------------------------------------------------
#define NRr     2000
#define NPp     1512
#define NTOT    3512          // NRr + NPp
#define DTOT    512           // ATT(256) + FUN(256)
#define BATCH   8192
#define FLATN   8192          // 32*2*128

// Scratch for hidden layers (device globals: no allocation allowed)
__device__ float g_h_att[(size_t)NTOT * 2048];
__device__ float g_h_fun[(size_t)NTOT * 4096];

// ---------------------------------------------------------------------------
// SGEMM: C[m, coloff+n] = act( sum_k A[m,k]*B[k,n] + bias[n] )
// A rows come from A1 (rows < splitM) or A2 (rows >= splitM). Row-major.
// act: 0 = exact gelu, 1 = sigmoid
// ---------------------------------------------------------------------------
#define BM 128
#define BN 128
#define BKK 8

__global__ __launch_bounds__(256)
void sgemm_act(const float* __restrict__ A1, const float* __restrict__ A2,
               int splitM, int M, int N, int K,
               const float* __restrict__ B, const float* __restrict__ bias,
               float* __restrict__ C, int ldc, int coloff, int act)
{
    __shared__ float As[BKK][BM + 4];
    __shared__ float Bs[BKK][BN];

    const int tid = threadIdx.x;
    const int bm = blockIdx.y * BM;
    const int bn = blockIdx.x * BN;

    // A-load mapping: 128 rows x 8 k, 4 scalars per thread
    const int arow = tid >> 1;           // 0..127
    const int ak0  = (tid & 1) * 4;      // 0 or 4
    const int m_a  = bm + arow;
    const float* aptr = nullptr;
    if (m_a < M)
        aptr = (m_a < splitM) ? (A1 + (size_t)m_a * K)
                              : (A2 + (size_t)(m_a - splitM) * K);

    // B-load mapping: 8 rows x 128 cols, one float4 per thread
    const int brow = tid >> 5;           // 0..7
    const int bcol = (tid & 31) * 4;     // 0..124

    const int ty = tid >> 4;             // 0..15
    const int tx = tid & 15;             // 0..15

    float acc[8][8];
    #pragma unroll
    for (int i = 0; i < 8; ++i)
        #pragma unroll
        for (int j = 0; j < 8; ++j) acc[i][j] = 0.f;

    for (int kt = 0; kt < K; kt += BKK) {
        // load A tile (scalar: K may be odd -> rows unaligned for float4)
        #pragma unroll
        for (int kk = 0; kk < 4; ++kk) {
            int k = kt + ak0 + kk;
            float v = 0.f;
            if (aptr && k < K) v = __ldg(aptr + k);
            As[ak0 + kk][arow] = v;
        }
        // load B tile (float4: all N are multiples of 4; rows 16B-aligned)
        {
            int k = kt + brow;
            float4 v = make_float4(0.f, 0.f, 0.f, 0.f);
            if (k < K) v = *(const float4*)(B + (size_t)k * N + bn + bcol);
            *(float4*)&Bs[brow][bcol] = v;
        }
        __syncthreads();

        #pragma unroll
        for (int k = 0; k < BKK; ++k) {
            float a[8], bb[8];
            *(float4*)&a[0]  = *(const float4*)&As[k][ty * 8];
            *(float4*)&a[4]  = *(const float4*)&As[k][ty * 8 + 4];
            *(float4*)&bb[0] = *(const float4*)&Bs[k][tx * 8];
            *(float4*)&bb[4] = *(const float4*)&Bs[k][tx * 8 + 4];
            #pragma unroll
            for (int i = 0; i < 8; ++i)
                #pragma unroll
                for (int j = 0; j < 8; ++j)
                    acc[i][j] = fmaf(a[i], bb[j], acc[i][j]);
        }
        __syncthreads();
    }

    // epilogue
    #pragma unroll
    for (int i = 0; i < 8; ++i) {
        int m = bm + ty * 8 + i;
        if (m >= M) continue;
        #pragma unroll
        for (int j = 0; j < 8; ++j) {
            int n = bn + tx * 8 + j;     // always < N (N % 128 == 0)
            float v = acc[i][j] + bias[n];
            if (act == 0) {
                // exact gelu: x * 0.5 * (1 + erf(x/sqrt(2)))
                v = 0.5f * v * (1.f + erff(v * 0.70710678118654752440f));
            } else {
                v = 1.f / (1.f + expf(-v));
            }
            C[(size_t)m * ldc + coloff + n] = v;
        }
    }
}

// ---------------------------------------------------------------------------
// Fused head: gather -> conv1(3x5,pad2) -> leaky -> avgpool2
//                    -> conv2(3x5,pad2) -> leaky -> maxpool2 -> tanh
//                    -> write flat + fused dot with W_out
// One block per pair. 256 threads.
// Input H=2 so only 1-2 kernel rows are ever valid per output row.
// ---------------------------------------------------------------------------
__device__ __forceinline__ float lrelu(float v) {
    return v >= 0.f ? v : 0.01f * v;
}

__global__ __launch_bounds__(256)
void conv_head(const float* __restrict__ e,      // [3512][512] (= start of d_out)
               const int* __restrict__ idx,
               const float* __restrict__ w1, const float* __restrict__ b1,
               const float* __restrict__ w2, const float* __restrict__ b2,
               const float* __restrict__ Wout, const float* __restrict__ bout,
               float* __restrict__ outp,          // [8192][2]
               float* __restrict__ flat)          // [8192][8192]
{
    extern __shared__ float sm[];
    float* w1s = sm;               // 240
    float* w2s = w1s + 240;        // 7680
    float* xs  = w2s + 7680;       // 2 * 520 (pad 2 each side + slack)
    float* h1s = xs + 1040;        // 32 rows (16c x 2r) x 260 (pad 2 each side)
    float* red = h1s + 8320;       // 16

    const int tid = threadIdx.x;
    const int b   = blockIdx.x;

    // stage weights, zero padded activation buffers
    for (int i = tid; i < 240;  i += 256) w1s[i] = w1[i];
    for (int i = tid; i < 7680; i += 256) w2s[i] = w2[i];
    for (int i = tid; i < 1040; i += 256) xs[i]  = 0.f;
    for (int i = tid; i < 8320; i += 256) h1s[i] = 0.f;
    __syncthreads();

    const int iv   = idx[b];
    const int r_no = iv / 1512;
    const int p_no = iv - r_no * 1512;
    const float* er = e + (size_t)r_no * DTOT;
    const float* ep = e + (size_t)(NRr + p_no) * DTOT;
    for (int i = tid; i < DTOT; i += 256) {
        xs[2 + i]       = er[i];
        xs[520 + 2 + i] = ep[i];
    }
    __syncthreads();

    // ---- conv1 + leaky + avgpool2: produce h1 [16][2][256] (padded cols) ----
    {
        const int q  = tid;        // 0..255 pooled column
        const int j0 = 2 * q;      // window xs[r][j0 .. j0+5] (pad already baked)
        for (int c = 0; c < 16; ++c) {
            float W0[5], W1[5], W2[5];
            #pragma unroll
            for (int kj = 0; kj < 5; ++kj) {
                W0[kj] = w1s[c * 15 + kj];
                W1[kj] = w1s[c * 15 + 5 + kj];
                W2[kj] = w1s[c * 15 + 10 + kj];
            }
            float X0[6], X1[6];
            #pragma unroll
            for (int t = 0; t < 6; ++t) {
                X0[t] = xs[j0 + t];
                X1[t] = xs[520 + j0 + t];
            }
            const float bb = b1[c];
            float v00 = bb, v01 = bb, v10 = bb, v11 = bb;
            float v20 = bb, v21 = bb, v30 = bb, v31 = bb;
            #pragma unroll
            for (int kj = 0; kj < 5; ++kj) {
                v00 = fmaf(W2[kj], X0[kj],     v00);   // i=0 (row0 via ki=2)
                v01 = fmaf(W2[kj], X0[kj + 1], v01);
                v10 = fmaf(W1[kj], X0[kj],     v10);   // i=1 (rows 0,1)
                v10 = fmaf(W2[kj], X1[kj],     v10);
                v11 = fmaf(W1[kj], X0[kj + 1], v11);
                v11 = fmaf(W2[kj], X1[kj + 1], v11);
                v20 = fmaf(W0[kj], X0[kj],     v20);   // i=2 (rows 0,1)
                v20 = fmaf(W1[kj], X1[kj],     v20);
                v21 = fmaf(W0[kj], X0[kj + 1], v21);
                v21 = fmaf(W1[kj], X1[kj + 1], v21);
                v30 = fmaf(W0[kj], X1[kj],     v30);   // i=3 (row1 via ki=0)
                v31 = fmaf(W0[kj], X1[kj + 1], v31);
            }
            float p0 = 0.25f * (lrelu(v00) + lrelu(v01) + lrelu(v10) + lrelu(v11));
            float p1 = 0.25f * (lrelu(v20) + lrelu(v21) + lrelu(v30) + lrelu(v31));
            h1s[(c * 2 + 0) * 260 + 2 + q] = p0;
            h1s[(c * 2 + 1) * 260 + 2 + q] = p1;
        }
    }
    __syncthreads();

    // ---- conv2 + leaky + maxpool2 + tanh + fused output dot ----
    const int qh = tid & 127;      // pooled column 0..127
    const int ph = tid >> 7;       // pooled row 0/1 (warps 0-3: ph=0)
    const int jb = 2 * qh;         // h1 window [jb .. jb+5] (pad baked)

    float d0 = 0.f, d1 = 0.f;
    for (int o = 0; o < 32; ++o) {
        const float bb = b2[o];
        float va = bb, vb = bb, vc = bb, vd = bb;  // (i0,j),(i0,j+1),(i1,j),(i1,j+1)
        for (int c = 0; c < 16; ++c) {
            float A0[6], A1v[6];
            #pragma unroll
            for (int t = 0; t < 6; ++t) {
                A0[t]  = h1s[(c * 2 + 0) * 260 + jb + t];
                A1v[t] = h1s[(c * 2 + 1) * 260 + jb + t];
            }
            const float* wp = &w2s[(o * 16 + c) * 15];
            if (ph == 0) {
                // i=0: ki=2 (row0); i=1: ki=1 (row0) + ki=2 (row1)
                #pragma unroll
                for (int kj = 0; kj < 5; ++kj) {
                    float w1k = wp[5 + kj], w2k = wp[10 + kj];
                    va = fmaf(w2k, A0[kj],      va);
                    vb = fmaf(w2k, A0[kj + 1],  vb);
                    vc = fmaf(w1k, A0[kj],      vc);
                    vc = fmaf(w2k, A1v[kj],     vc);
                    vd = fmaf(w1k, A0[kj + 1],  vd);
                    vd = fmaf(w2k, A1v[kj + 1], vd);
                }
            } else {
                // i=2: ki=0 (row0) + ki=1 (row1); i=3: ki=0 (row1)
                #pragma unroll
                for (int kj = 0; kj < 5; ++kj) {
                    float w0k = wp[kj], w1k = wp[5 + kj];
                    va = fmaf(w0k, A0[kj],      va);
                    va = fmaf(w1k, A1v[kj],     va);
                    vb = fmaf(w0k, A0[kj + 1],  vb);
                    vb = fmaf(w1k, A1v[kj + 1], vb);
                    vc = fmaf(w0k, A1v[kj],     vc);
                    vd = fmaf(w0k, A1v[kj + 1], vd);
                }
            }
        }
        float mx = fmaxf(fmaxf(lrelu(va), lrelu(vb)), fmaxf(lrelu(vc), lrelu(vd)));
        float t  = tanhf(mx);
        int k = o * 256 + tid;                     // = o*256 + ph*128 + qh
        flat[(size_t)b * FLATN + k] = t;
        float2 wv = __ldg(((const float2*)Wout) + k);
        d0 = fmaf(t, wv.x, d0);
        d1 = fmaf(t, wv.y, d1);
    }

    // block reduction for the 2-wide output GEMM
    #pragma unroll
    for (int off = 16; off > 0; off >>= 1) {
        d0 += __shfl_down_sync(0xffffffffu, d0, off);
        d1 += __shfl_down_sync(0xffffffffu, d1, off);
    }
    const int w = tid >> 5, lane = tid & 31;
    if (lane == 0) { red[w * 2] = d0; red[w * 2 + 1] = d1; }
    __syncthreads();
    if (tid == 0) {
        float s0 = 0.f, s1 = 0.f;
        #pragma unroll
        for (int i = 0; i < 8; ++i) { s0 += red[i * 2]; s1 += red[i * 2 + 1]; }
        outp[(size_t)b * 2 + 0] = s0 + bout[0];
        outp[(size_t)b * 2 + 1] = s1 + bout[1];
    }
}

// ---------------------------------------------------------------------------
// kernel_launch
// ---------------------------------------------------------------------------
extern "C" void kernel_launch(void* const* d_in, const int* in_sizes, int n_in,
                              void* d_out, int out_size)
{
    const float* r_att   = (const float*)d_in[0];
    const float* p_att   = (const float*)d_in[1];
    const float* r_fun   = (const float*)d_in[2];
    const float* p_fun   = (const float*)d_in[3];
    const int*   idx     = (const int*)  d_in[4];
    const float* W_att1  = (const float*)d_in[5];
    const float* b_att1  = (const float*)d_in[6];
    const float* W_att2  = (const float*)d_in[7];
    const float* b_att2  = (const float*)d_in[8];
    const float* W_fun1  = (const float*)d_in[9];
    const float* b_fun1  = (const float*)d_in[10];
    const float* W_fun2  = (const float*)d_in[11];
    const float* b_fun2  = (const float*)d_in[12];
    const float* conv1_w = (const float*)d_in[13];
    const float* conv1_b = (const float*)d_in[14];
    const float* conv2_w = (const float*)d_in[15];
    const float* conv2_b = (const float*)d_in[16];
    const float* W_out   = (const float*)d_in[17];
    const float* b_out   = (const float*)d_in[18];

    float* out  = (float*)d_out;
    float* e    = out;                                   // [3512][512]
    float* outp = out + (size_t)NTOT * DTOT;             // [8192][2]
    float* flat = outp + (size_t)BATCH * 2;              // [8192][8192]

    float* hatt = nullptr; cudaGetSymbolAddress((void**)&hatt, g_h_att);
    float* hfun = nullptr; cudaGetSymbolAddress((void**)&hfun, g_h_fun);

    dim3 blk(256);
    // att1: [3512,3000] x [3000,2048] -> gelu
    sgemm_act<<<dim3(2048 / BN, (NTOT + BM - 1) / BM), blk>>>(
        r_att, p_att, NRr, NTOT, 2048, 3000, W_att1, b_att1, hatt, 2048, 0, 0);
    // fun1: [3512,5603] x [5603,4096] -> gelu
    sgemm_act<<<dim3(4096 / BN, (NTOT + BM - 1) / BM), blk>>>(
        r_fun, p_fun, NRr, NTOT, 4096, 5603, W_fun1, b_fun1, hfun, 4096, 0, 0);
    // att2: [3512,2048] x [2048,256] -> sigmoid -> e[:, 0:256]
    sgemm_act<<<dim3(256 / BN, (NTOT + BM - 1) / BM), blk>>>(
        hatt, nullptr, NTOT, NTOT, 256, 2048, W_att2, b_att2, e, DTOT, 0, 1);
    // fun2: [3512,4096] x [4096,256] -> sigmoid -> e[:, 256:512]
    sgemm_act<<<dim3(256 / BN, (NTOT + BM - 1) / BM), blk>>>(
        hfun, nullptr, NTOT, NTOT, 256, 4096, W_fun2, b_fun2, e, DTOT, 256, 1);

    // fused conv head
    const int smem_bytes = (240 + 7680 + 1040 + 8320 + 16) * 4;  // 69184
    cudaFuncSetAttribute(conv_head, cudaFuncAttributeMaxDynamicSharedMemorySize,
                         smem_bytes);
    conv_head<<<BATCH, 256, smem_bytes>>>(
        e, idx, conv1_w, conv1_b, conv2_w, conv2_b, W_out, b_out, outp, flat);
}

// round 2
// speedup vs baseline: 2.0615x; 2.0615x over previous
#include <cuda_runtime.h>
#include <cstdint>

// ---------------------------------------------------------------------------
// Problem constants
// ---------------------------------------------------------------------------
#define NRr     2000
#define NPp     1512
#define NTOT    3512          // NRr + NPp
#define DTOT    512           // ATT(256) + FUN(256)
#define BATCH   8192
#define FLATN   8192          // 32*2*128
#define KFUN    5603
#define KFP     5604          // padded (multiple of 4)

// Scratch (device globals: no allocation allowed)
__device__ float g_h_att[(size_t)NTOT * 2048];
__device__ float g_h_fun[(size_t)NTOT * 4096];
__device__ float g_afun [(size_t)NTOT * KFP];

// ---------------------------------------------------------------------------
// TF32 mma helpers
// ---------------------------------------------------------------------------
__device__ __forceinline__ uint32_t f2tf32(float f) {
    uint32_t r;
    asm("cvt.rna.tf32.f32 %0, %1;" : "=r"(r) : "f"(f));
    return r;
}

__device__ __forceinline__ void mma8(float* d, const uint32_t* a, const uint32_t* b) {
    asm volatile(
        "mma.sync.aligned.m16n8k8.row.col.f32.tf32.tf32.f32 "
        "{%0,%1,%2,%3},{%4,%5,%6,%7},{%8,%9},{%0,%1,%2,%3};"
        : "+f"(d[0]), "+f"(d[1]), "+f"(d[2]), "+f"(d[3])
        : "r"(a[0]), "r"(a[1]), "r"(a[2]), "r"(a[3]), "r"(b[0]), "r"(b[1]));
}

__device__ __forceinline__ void cpa16(float* smem_dst, const float* g, bool pred) {
    uint32_t s = (uint32_t)__cvta_generic_to_shared(smem_dst);
    int sz = pred ? 16 : 0;
    asm volatile("cp.async.cg.shared.global [%0], [%1], 16, %2;"
                 :: "r"(s), "l"(g), "r"(sz));
}

// ---------------------------------------------------------------------------
// Pad fun inputs into g_afun [NTOT][KFP] (zero col 5603) so rows are 16B-ok
// ---------------------------------------------------------------------------
__global__ void pad_fun(const float* __restrict__ r, const float* __restrict__ p) {
    int row = blockIdx.y;
    const float* src = (row < NRr) ? (r + (size_t)row * KFUN)
                                   : (p + (size_t)(row - NRr) * KFUN);
    float* dst = g_afun + (size_t)row * KFP;
    int c = blockIdx.x * blockDim.x + threadIdx.x;
    if (c < KFP) dst[c] = (c < KFUN) ? src[c] : 0.f;
}

// ---------------------------------------------------------------------------
// TF32 tensor-core GEMM: C[m, coloff+n] = act(sum_k A[m,k]*B[k,n] + bias[n])
// A rows: A1 (m < splitM) else A2 (row m - splitM), row stride lda.
// A zero-filled for k >= KA (KA % 4 == 0). B valid for k < K.
// BN = 128, BK = 16, 256 threads, 8 warps in 4x2, warp tile (BM/4) x 64.
// ACT: 0 = exact gelu, 1 = sigmoid
// ---------------------------------------------------------------------------
template<int BM, int ACT>
__global__ __launch_bounds__(256)
void mma_gemm(const float* __restrict__ A1, const float* __restrict__ A2,
              int splitM, int lda, int M, int N, int K, int KA,
              const float* __restrict__ B, const float* __restrict__ bias,
              float* __restrict__ C, int ldc, int coloff)
{
    constexpr int BN = 128, BK = 16;
    constexpr int AS = 20;          // As row stride (words) - conflict-free
    constexpr int BS = 136;         // Bs row stride (words) - conflict-free
    constexpr int WM = BM / 4;
    constexpr int MI = WM / 16;

    __shared__ __align__(16) float As[2][BM * AS];
    __shared__ __align__(16) float Bs[2][BK * BS];

    const int tid  = threadIdx.x;
    const int lane = tid & 31, warp = tid >> 5;
    const int wm = warp >> 1, wn = warp & 1;
    const int bm = blockIdx.y * BM, bn = blockIdx.x * BN;

    // A-load mapping (float4 granules)
    int ar, ak;
    if (BM == 128) { ar = tid >> 1; ak = (tid & 1) * 8; }   // 2 float4/thread
    else           { ar = tid >> 2; ak = (tid & 3) * 4; }   // 1 float4/thread
    const int am  = bm + ar;
    const bool amv = (am < M);
    const float* arow;
    {
        int mc = amv ? am : 0;
        arow = (mc < splitM) ? (A1 + (size_t)mc * lda)
                             : (A2 + (size_t)(mc - splitM) * lda);
    }

    // B-load mapping: 2 float4/thread
    const int bk = tid >> 5;            // 0..7
    const int bc = (tid & 31) * 4;      // 0..124

    float acc[MI][8][4];
    #pragma unroll
    for (int i = 0; i < MI; ++i)
        #pragma unroll
        for (int j = 0; j < 8; ++j)
            #pragma unroll
            for (int q = 0; q < 4; ++q) acc[i][j][q] = 0.f;

    const int nIt = (K + BK - 1) / BK;

    auto load_stage = [&](int st, int kt) {
        if (BM == 128) {
            #pragma unroll
            for (int u = 0; u < 2; ++u) {
                int k = kt + ak + u * 4;
                bool p = amv && (k < KA);
                cpa16(&As[st][ar * AS + ak + u * 4], p ? (arow + k) : A1, p);
            }
        } else {
            int k = kt + ak;
            bool p = amv && (k < KA);
            cpa16(&As[st][ar * AS + ak], p ? (arow + k) : A1, p);
        }
        #pragma unroll
        for (int u = 0; u < 2; ++u) {
            int k = kt + bk + u * 8;
            bool p = (k < K);
            cpa16(&Bs[st][(bk + u * 8) * BS + bc],
                  p ? (B + (size_t)k * N + bn + bc) : B, p);
        }
        asm volatile("cp.async.commit_group;");
    };

    load_stage(0, 0);

    for (int it = 0; it < nIt; ++it) {
        const int cur = it & 1;
        if (it + 1 < nIt) load_stage(cur ^ 1, (it + 1) * BK);
        else              asm volatile("cp.async.commit_group;");
        asm volatile("cp.async.wait_group 1;");
        __syncthreads();

        const float* as = As[cur];
        const float* bs = Bs[cur];
        #pragma unroll
        for (int kk = 0; kk < BK; kk += 8) {
            uint32_t af[MI][4];
            #pragma unroll
            for (int mi = 0; mi < MI; ++mi) {
                int r0 = wm * WM + mi * 16 + (lane >> 2);
                int c0 = kk + (lane & 3);
                af[mi][0] = f2tf32(as[ r0      * AS + c0    ]);
                af[mi][1] = f2tf32(as[(r0 + 8) * AS + c0    ]);
                af[mi][2] = f2tf32(as[ r0      * AS + c0 + 4]);
                af[mi][3] = f2tf32(as[(r0 + 8) * AS + c0 + 4]);
            }
            uint32_t bf[8][2];
            #pragma unroll
            for (int ni = 0; ni < 8; ++ni) {
                int c = wn * 64 + ni * 8 + (lane >> 2);
                bf[ni][0] = f2tf32(bs[(kk + (lane & 3)    ) * BS + c]);
                bf[ni][1] = f2tf32(bs[(kk + (lane & 3) + 4) * BS + c]);
            }
            #pragma unroll
            for (int mi = 0; mi < MI; ++mi)
                #pragma unroll
                for (int ni = 0; ni < 8; ++ni)
                    mma8(acc[mi][ni], af[mi], bf[ni]);
        }
        __syncthreads();
    }

    // epilogue: bias + activation, float2 stores
    #pragma unroll
    for (int mi = 0; mi < MI; ++mi) {
        #pragma unroll
        for (int ni = 0; ni < 8; ++ni) {
            int m0 = bm + wm * WM + mi * 16 + (lane >> 2);
            int n  = bn + wn * 64 + ni * 8 + (lane & 3) * 2;
            float bi0 = bias[n], bi1 = bias[n + 1];
            #pragma unroll
            for (int h = 0; h < 2; ++h) {
                int m = m0 + h * 8;
                if (m < M) {
                    float v0 = acc[mi][ni][h * 2 + 0] + bi0;
                    float v1 = acc[mi][ni][h * 2 + 1] + bi1;
                    if (ACT == 0) {
                        v0 = 0.5f * v0 * (1.f + erff(v0 * 0.70710678118654752f));
                        v1 = 0.5f * v1 * (1.f + erff(v1 * 0.70710678118654752f));
                    } else {
                        v0 = 1.f / (1.f + expf(-v0));
                        v1 = 1.f / (1.f + expf(-v1));
                    }
                    *(float2*)&C[(size_t)m * ldc + coloff + n] = make_float2(v0, v1);
                }
            }
        }
    }
}

// ---------------------------------------------------------------------------
// Fused head (unchanged from passing R1 kernel):
// gather -> conv1 -> leaky -> avgpool2 -> conv2 -> leaky -> maxpool2 -> tanh
// -> flat + fused dot with W_out. One block per pair, 256 threads.
// ---------------------------------------------------------------------------
__device__ __forceinline__ float lrelu(float v) {
    return v >= 0.f ? v : 0.01f * v;
}

__global__ __launch_bounds__(256)
void conv_head(const float* __restrict__ e,
               const int* __restrict__ idx,
               const float* __restrict__ w1, const float* __restrict__ b1,
               const float* __restrict__ w2, const float* __restrict__ b2,
               const float* __restrict__ Wout, const float* __restrict__ bout,
               float* __restrict__ outp,
               float* __restrict__ flat)
{
    extern __shared__ float sm[];
    float* w1s = sm;               // 240
    float* w2s = w1s + 240;        // 7680
    float* xs  = w2s + 7680;       // 2 * 520
    float* h1s = xs + 1040;        // 32 x 260
    float* red = h1s + 8320;       // 16

    const int tid = threadIdx.x;
    const int b   = blockIdx.x;

    for (int i = tid; i < 240;  i += 256) w1s[i] = w1[i];
    for (int i = tid; i < 7680; i += 256) w2s[i] = w2[i];
    for (int i = tid; i < 1040; i += 256) xs[i]  = 0.f;
    for (int i = tid; i < 8320; i += 256) h1s[i] = 0.f;
    __syncthreads();

    const int iv   = idx[b];
    const int r_no = iv / 1512;
    const int p_no = iv - r_no * 1512;
    const float* er = e + (size_t)r_no * DTOT;
    const float* ep = e + (size_t)(NRr + p_no) * DTOT;
    for (int i = tid; i < DTOT; i += 256) {
        xs[2 + i]       = er[i];
        xs[520 + 2 + i] = ep[i];
    }
    __syncthreads();

    // conv1 + leaky + avgpool2 -> h1 [16][2][256] (padded cols)
    {
        const int q  = tid;
        const int j0 = 2 * q;
        for (int c = 0; c < 16; ++c) {
            float W0[5], W1[5], W2[5];
            #pragma unroll
            for (int kj = 0; kj < 5; ++kj) {
                W0[kj] = w1s[c * 15 + kj];
                W1[kj] = w1s[c * 15 + 5 + kj];
                W2[kj] = w1s[c * 15 + 10 + kj];
            }
            float X0[6], X1[6];
            #pragma unroll
            for (int t = 0; t < 6; ++t) {
                X0[t] = xs[j0 + t];
                X1[t] = xs[520 + j0 + t];
            }
            const float bb = b1[c];
            float v00 = bb, v01 = bb, v10 = bb, v11 = bb;
            float v20 = bb, v21 = bb, v30 = bb, v31 = bb;
            #pragma unroll
            for (int kj = 0; kj < 5; ++kj) {
                v00 = fmaf(W2[kj], X0[kj],     v00);
                v01 = fmaf(W2[kj], X0[kj + 1], v01);
                v10 = fmaf(W1[kj], X0[kj],     v10);
                v10 = fmaf(W2[kj], X1[kj],     v10);
                v11 = fmaf(W1[kj], X0[kj + 1], v11);
                v11 = fmaf(W2[kj], X1[kj + 1], v11);
                v20 = fmaf(W0[kj], X0[kj],     v20);
                v20 = fmaf(W1[kj], X1[kj],     v20);
                v21 = fmaf(W0[kj], X0[kj + 1], v21);
                v21 = fmaf(W1[kj], X1[kj + 1], v21);
                v30 = fmaf(W0[kj], X1[kj],     v30);
                v31 = fmaf(W0[kj], X1[kj + 1], v31);
            }
            float p0 = 0.25f * (lrelu(v00) + lrelu(v01) + lrelu(v10) + lrelu(v11));
            float p1 = 0.25f * (lrelu(v20) + lrelu(v21) + lrelu(v30) + lrelu(v31));
            h1s[(c * 2 + 0) * 260 + 2 + q] = p0;
            h1s[(c * 2 + 1) * 260 + 2 + q] = p1;
        }
    }
    __syncthreads();

    // conv2 + leaky + maxpool2 + tanh + fused dot
    const int qh = tid & 127;
    const int ph = tid >> 7;
    const int jb = 2 * qh;

    float d0 = 0.f, d1 = 0.f;
    for (int o = 0; o < 32; ++o) {
        const float bb = b2[o];
        float va = bb, vb = bb, vc = bb, vd = bb;
        for (int c = 0; c < 16; ++c) {
            float A0[6], A1v[6];
            #pragma unroll
            for (int t = 0; t < 6; ++t) {
                A0[t]  = h1s[(c * 2 + 0) * 260 + jb + t];
                A1v[t] = h1s[(c * 2 + 1) * 260 + jb + t];
            }
            const float* wp = &w2s[(o * 16 + c) * 15];
            if (ph == 0) {
                #pragma unroll
                for (int kj = 0; kj < 5; ++kj) {
                    float w1k = wp[5 + kj], w2k = wp[10 + kj];
                    va = fmaf(w2k, A0[kj],      va);
                    vb = fmaf(w2k, A0[kj + 1],  vb);
                    vc = fmaf(w1k, A0[kj],      vc);
                    vc = fmaf(w2k, A1v[kj],     vc);
                    vd = fmaf(w1k, A0[kj + 1],  vd);
                    vd = fmaf(w2k, A1v[kj + 1], vd);
                }
            } else {
                #pragma unroll
                for (int kj = 0; kj < 5; ++kj) {
                    float w0k = wp[kj], w1k = wp[5 + kj];
                    va = fmaf(w0k, A0[kj],      va);
                    va = fmaf(w1k, A1v[kj],     va);
                    vb = fmaf(w0k, A0[kj + 1],  vb);
                    vb = fmaf(w1k, A1v[kj + 1], vb);
                    vc = fmaf(w0k, A1v[kj],     vc);
                    vd = fmaf(w0k, A1v[kj + 1], vd);
                }
            }
        }
        float mx = fmaxf(fmaxf(lrelu(va), lrelu(vb)), fmaxf(lrelu(vc), lrelu(vd)));
        float t  = tanhf(mx);
        int k = o * 256 + tid;
        flat[(size_t)b * FLATN + k] = t;
        float2 wv = __ldg(((const float2*)Wout) + k);
        d0 = fmaf(t, wv.x, d0);
        d1 = fmaf(t, wv.y, d1);
    }

    #pragma unroll
    for (int off = 16; off > 0; off >>= 1) {
        d0 += __shfl_down_sync(0xffffffffu, d0, off);
        d1 += __shfl_down_sync(0xffffffffu, d1, off);
    }
    const int w = tid >> 5, lane = tid & 31;
    if (lane == 0) { red[w * 2] = d0; red[w * 2 + 1] = d1; }
    __syncthreads();
    if (tid == 0) {
        float s0 = 0.f, s1 = 0.f;
        #pragma unroll
        for (int i = 0; i < 8; ++i) { s0 += red[i * 2]; s1 += red[i * 2 + 1]; }
        outp[(size_t)b * 2 + 0] = s0 + bout[0];
        outp[(size_t)b * 2 + 1] = s1 + bout[1];
    }
}

// ---------------------------------------------------------------------------
// kernel_launch
// ---------------------------------------------------------------------------
extern "C" void kernel_launch(void* const* d_in, const int* in_sizes, int n_in,
                              void* d_out, int out_size)
{
    const float* r_att   = (const float*)d_in[0];
    const float* p_att   = (const float*)d_in[1];
    const float* r_fun   = (const float*)d_in[2];
    const float* p_fun   = (const float*)d_in[3];
    const int*   idx     = (const int*)  d_in[4];
    const float* W_att1  = (const float*)d_in[5];
    const float* b_att1  = (const float*)d_in[6];
    const float* W_att2  = (const float*)d_in[7];
    const float* b_att2  = (const float*)d_in[8];
    const float* W_fun1  = (const float*)d_in[9];
    const float* b_fun1  = (const float*)d_in[10];
    const float* W_fun2  = (const float*)d_in[11];
    const float* b_fun2  = (const float*)d_in[12];
    const float* conv1_w = (const float*)d_in[13];
    const float* conv1_b = (const float*)d_in[14];
    const float* conv2_w = (const float*)d_in[15];
    const float* conv2_b = (const float*)d_in[16];
    const float* W_out   = (const float*)d_in[17];
    const float* b_out   = (const float*)d_in[18];

    float* out  = (float*)d_out;
    float* e    = out;                                   // [3512][512]
    float* outp = out + (size_t)NTOT * DTOT;             // [8192][2]
    float* flat = outp + (size_t)BATCH * 2;              // [8192][8192]

    float* hatt = nullptr; cudaGetSymbolAddress((void**)&hatt, g_h_att);
    float* hfun = nullptr; cudaGetSymbolAddress((void**)&hfun, g_h_fun);
    float* afun = nullptr; cudaGetSymbolAddress((void**)&afun, g_afun);

    // pad fun inputs for aligned cp.async
    pad_fun<<<dim3((KFP + 1023) / 1024, NTOT), 1024>>>(r_fun, p_fun);

    // att1: [3512,3000] x [3000,2048] -> gelu
    mma_gemm<128, 0><<<dim3(2048 / 128, (NTOT + 127) / 128), 256>>>(
        r_att, p_att, NRr, 3000, NTOT, 2048, 3000, 3000, W_att1, b_att1,
        hatt, 2048, 0);
    // fun1: [3512,5603] x [5603,4096] -> gelu (padded A)
    mma_gemm<128, 0><<<dim3(4096 / 128, (NTOT + 127) / 128), 256>>>(
        afun, afun, NTOT, KFP, NTOT, 4096, KFUN, KFP, W_fun1, b_fun1,
        hfun, 4096, 0);
    // att2: [3512,2048] x [2048,256] -> sigmoid -> e[:, 0:256]
    mma_gemm<64, 1><<<dim3(256 / 128, (NTOT + 63) / 64), 256>>>(
        hatt, hatt, NTOT, 2048, NTOT, 256, 2048, 2048, W_att2, b_att2,
        e, DTOT, 0);
    // fun2: [3512,4096] x [4096,256] -> sigmoid -> e[:, 256:512]
    mma_gemm<64, 1><<<dim3(256 / 128, (NTOT + 63) / 64), 256>>>(
        hfun, hfun, NTOT, 4096, NTOT, 256, 4096, 4096, W_fun2, b_fun2,
        e, DTOT, 256);

    // fused conv head
    const int smem_bytes = (240 + 7680 + 1040 + 8320 + 16) * 4;  // 69184
    cudaFuncSetAttribute(conv_head, cudaFuncAttributeMaxDynamicSharedMemorySize,
                         smem_bytes);
    conv_head<<<BATCH, 256, smem_bytes>>>(
        e, idx, conv1_w, conv1_b, conv2_w, conv2_b, W_out, b_out, outp, flat);
}

// round 3
// speedup vs baseline: 3.2272x; 1.5655x over previous
#include <cuda_runtime.h>
#include <cstdint>

// ---------------------------------------------------------------------------
// Problem constants
// ---------------------------------------------------------------------------
#define NRr     2000
#define NPp     1512
#define NTOT    3512          // NRr + NPp
#define DTOT    512           // ATT(256) + FUN(256)
#define BATCH   8192
#define FLATN   8192          // 32*2*128
#define KATT    3000
#define KFUN    5603
#define KFP     5604          // padded (multiple of 4)

// Scratch (device globals: allocation is forbidden)
__device__ float g_h_att[(size_t)NTOT * 2048];
__device__ float g_h_fun[(size_t)NTOT * 4096];
__device__ float g_aatt [(size_t)NTOT * KATT];
__device__ float g_afun [(size_t)NTOT * KFP];
__device__ float g_w1a  [(size_t)KATT * 2048];
__device__ float g_w1f  [(size_t)KFUN * 4096];
__device__ float g_w2a  [(size_t)2048 * 256];
__device__ float g_w2f  [(size_t)4096 * 256];

// ---------------------------------------------------------------------------
// helpers
// ---------------------------------------------------------------------------
__device__ __forceinline__ uint32_t f2tf32(float f) {
    uint32_t r;
    asm("cvt.rna.tf32.f32 %0, %1;" : "=r"(r) : "f"(f));
    return r;
}
__device__ __forceinline__ float tf32r(float f) {
    return __uint_as_float(f2tf32(f));
}

__device__ __forceinline__ void mma8(float* d, const uint32_t* a, const uint32_t* b) {
    asm volatile(
        "mma.sync.aligned.m16n8k8.row.col.f32.tf32.tf32.f32 "
        "{%0,%1,%2,%3},{%4,%5,%6,%7},{%8,%9},{%0,%1,%2,%3};"
        : "+f"(d[0]), "+f"(d[1]), "+f"(d[2]), "+f"(d[3])
        : "r"(a[0]), "r"(a[1]), "r"(a[2]), "r"(a[3]), "r"(b[0]), "r"(b[1]));
}

__device__ __forceinline__ void cpa16(float* smem_dst, const float* g, bool pred) {
    uint32_t s = (uint32_t)__cvta_generic_to_shared(smem_dst);
    int sz = pred ? 16 : 0;
    asm volatile("cp.async.cg.shared.global [%0], [%1], 16, %2;"
                 :: "r"(s), "l"(g), "r"(sz));
}

__device__ __forceinline__ float lrelu(float v) {
    return v >= 0.f ? v : 0.01f * v;
}

// ---------------------------------------------------------------------------
// Prepass: round-to-tf32 copies (so GEMM inner loops need no cvt)
// ---------------------------------------------------------------------------
__global__ void rc4(float4* __restrict__ dst, const float4* __restrict__ src, int n4) {
    int i = blockIdx.x * blockDim.x + threadIdx.x;
    if (i < n4) {
        float4 v = src[i];
        v.x = tf32r(v.x); v.y = tf32r(v.y); v.z = tf32r(v.z); v.w = tf32r(v.w);
        dst[i] = v;
    }
}

__global__ void pad_fun(const float* __restrict__ r, const float* __restrict__ p) {
    int row = blockIdx.y;
    const float* src = (row < NRr) ? (r + (size_t)row * KFUN)
                                   : (p + (size_t)(row - NRr) * KFUN);
    float* dst = g_afun + (size_t)row * KFP;
    int c = blockIdx.x * blockDim.x + threadIdx.x;
    if (c < KFP) dst[c] = (c < KFUN) ? tf32r(src[c]) : 0.f;
}

// ---------------------------------------------------------------------------
// TF32 tensor-core GEMM, 3-stage cp.async pipeline.
// C[m, coloff+n] = act(sum_k A[m,k]*B[k,n] + bias[n]); A/B pre-rounded tf32.
// A rows: A1 if m<splitM else A2[m-splitM], row stride lda; zero for k>=KA.
// BN=128, BK=16, 256 thr, 8 warps 4x2, warp tile (BM/4) x 64.
// ACT: 0 gelu, 1 sigmoid.  ROUND: round output to tf32 (for next-layer A).
// ---------------------------------------------------------------------------
template<int BM, int ACT, int ROUND>
__global__ __launch_bounds__(256, 2)
void mma_gemm(const float* __restrict__ A1, const float* __restrict__ A2,
              int splitM, int lda, int M, int N, int K, int KA,
              const float* __restrict__ B, const float* __restrict__ bias,
              float* __restrict__ C, int ldc, int coloff)
{
    constexpr int BN = 128, BK = 16, ST = 3;
    constexpr int AS = 20;          // As row stride (words)
    constexpr int BS = 136;         // Bs row stride (words)
    constexpr int WM = BM / 4;
    constexpr int MI = WM / 16;
    constexpr int ASZ = BM * AS;
    constexpr int BSZ = BK * BS;

    extern __shared__ float dsm[];
    float* As = dsm;                // ST * ASZ
    float* Bs = dsm + ST * ASZ;     // ST * BSZ

    const int tid  = threadIdx.x;
    const int lane = tid & 31, warp = tid >> 5;
    const int wm = warp >> 1, wn = warp & 1;
    const int bm = blockIdx.y * BM, bn = blockIdx.x * BN;

    int ar, ak;
    if (BM == 128) { ar = tid >> 1; ak = (tid & 1) * 8; }
    else           { ar = tid >> 2; ak = (tid & 3) * 4; }
    const int am  = bm + ar;
    const bool amv = (am < M);
    const float* arow;
    {
        int mc = amv ? am : 0;
        arow = (mc < splitM) ? (A1 + (size_t)mc * lda)
                             : (A2 + (size_t)(mc - splitM) * lda);
    }
    const int bk = tid >> 5;
    const int bc = (tid & 31) * 4;

    float acc[MI][8][4];
    #pragma unroll
    for (int i = 0; i < MI; ++i)
        #pragma unroll
        for (int j = 0; j < 8; ++j)
            #pragma unroll
            for (int q = 0; q < 4; ++q) acc[i][j][q] = 0.f;

    const int nIt = (K + BK - 1) / BK;

    auto load_stage = [&](int st, int kt) {
        float* as = As + st * ASZ;
        float* bs = Bs + st * BSZ;
        if (BM == 128) {
            #pragma unroll
            for (int u = 0; u < 2; ++u) {
                int k = kt + ak + u * 4;
                bool p = amv && (k < KA);
                cpa16(&as[ar * AS + ak + u * 4], p ? (arow + k) : A1, p);
            }
        } else {
            int k = kt + ak;
            bool p = amv && (k < KA);
            cpa16(&as[ar * AS + ak], p ? (arow + k) : A1, p);
        }
        #pragma unroll
        for (int u = 0; u < 2; ++u) {
            int k = kt + bk + u * 8;
            bool p = (k < K);
            cpa16(&bs[(bk + u * 8) * BS + bc],
                  p ? (B + (size_t)k * N + bn + bc) : B, p);
        }
        asm volatile("cp.async.commit_group;");
    };

    load_stage(0, 0);
    load_stage(1, BK);

    for (int it = 0; it < nIt; ++it) {
        const int cur = it % ST;
        asm volatile("cp.async.wait_group 1;");
        __syncthreads();

        int nx = it + ST - 1;
        if (nx < nIt) load_stage(nx % ST, nx * BK);
        else          asm volatile("cp.async.commit_group;");

        const float* as = As + cur * ASZ;
        const float* bs = Bs + cur * BSZ;
        const uint32_t* asu = (const uint32_t*)as;
        const uint32_t* bsu = (const uint32_t*)bs;
        #pragma unroll
        for (int kk = 0; kk < BK; kk += 8) {
            uint32_t af[MI][4];
            #pragma unroll
            for (int mi = 0; mi < MI; ++mi) {
                int r0 = wm * WM + mi * 16 + (lane >> 2);
                int c0 = kk + (lane & 3);
                af[mi][0] = asu[ r0      * AS + c0    ];
                af[mi][1] = asu[(r0 + 8) * AS + c0    ];
                af[mi][2] = asu[ r0      * AS + c0 + 4];
                af[mi][3] = asu[(r0 + 8) * AS + c0 + 4];
            }
            uint32_t bf[8][2];
            #pragma unroll
            for (int ni = 0; ni < 8; ++ni) {
                int c = wn * 64 + ni * 8 + (lane >> 2);
                bf[ni][0] = bsu[(kk + (lane & 3)    ) * BS + c];
                bf[ni][1] = bsu[(kk + (lane & 3) + 4) * BS + c];
            }
            #pragma unroll
            for (int mi = 0; mi < MI; ++mi)
                #pragma unroll
                for (int ni = 0; ni < 8; ++ni)
                    mma8(acc[mi][ni], af[mi], bf[ni]);
        }
        __syncthreads();
    }

    #pragma unroll
    for (int mi = 0; mi < MI; ++mi) {
        #pragma unroll
        for (int ni = 0; ni < 8; ++ni) {
            int m0 = bm + wm * WM + mi * 16 + (lane >> 2);
            int n  = bn + wn * 64 + ni * 8 + (lane & 3) * 2;
            float bi0 = bias[n], bi1 = bias[n + 1];
            #pragma unroll
            for (int h = 0; h < 2; ++h) {
                int m = m0 + h * 8;
                if (m < M) {
                    float v0 = acc[mi][ni][h * 2 + 0] + bi0;
                    float v1 = acc[mi][ni][h * 2 + 1] + bi1;
                    if (ACT == 0) {
                        v0 = 0.5f * v0 * (1.f + erff(v0 * 0.70710678118654752f));
                        v1 = 0.5f * v1 * (1.f + erff(v1 * 0.70710678118654752f));
                    } else {
                        v0 = 1.f / (1.f + expf(-v0));
                        v1 = 1.f / (1.f + expf(-v1));
                    }
                    if (ROUND) { v0 = tf32r(v0); v1 = tf32r(v1); }
                    *(float2*)&C[(size_t)m * ldc + coloff + n] = make_float2(v0, v1);
                }
            }
        }
    }
}

// ---------------------------------------------------------------------------
// Fused head. One block per pair, 256 threads (8 warps).
// conv1 scalar (cheap) -> h1 in smem (tf32-rounded).
// conv2 as implicit-im2col TF32 MMA: M=1024 positions (4 i x 256 j),
// K=240 (16c x 3ki x 5kj), N=32. Invalid kernel rows -> zero row 32.
// Then lrelu, maxpool (shfl j-pairs, register i-pairs), tanh,
// staged to smem, coalesced flat write + fused W_out dot.
// ---------------------------------------------------------------------------
#define W2S 244
#define H1W 260

__global__ __launch_bounds__(256)
void conv_head(const float* __restrict__ e,
               const int* __restrict__ idx,
               const float* __restrict__ w1, const float* __restrict__ b1,
               const float* __restrict__ w2, const float* __restrict__ b2,
               const float* __restrict__ Wout, const float* __restrict__ bout,
               float* __restrict__ outp,
               float* __restrict__ flat)
{
    extern __shared__ float sm[];
    float* w1s  = sm;                 // 240
    float* w2s  = sm + 240;           // 32*244 = 7808
    float* xs   = sm + 8048;          // 1040
    float* h1s  = sm + 9088;          // 33*260 = 8580 (row 32 = zero row)
    float* pool = sm + 17668;         // 256*33 = 8448
    float* red  = sm + 26116;         // 16
    const uint32_t* h1u = (const uint32_t*)h1s;
    const uint32_t* w2u = (const uint32_t*)w2s;

    const int tid = threadIdx.x;
    const int lane = tid & 31, w = tid >> 5;
    const int b = blockIdx.x;

    for (int i = tid; i < 240; i += 256) w1s[i] = w1[i];
    for (int i = tid; i < 7680; i += 256) {
        int o = i / 240, k = i - o * 240;
        w2s[o * W2S + k] = tf32r(w2[i]);
    }
    for (int i = tid; i < 1040; i += 256) xs[i] = 0.f;
    for (int i = tid; i < 8580; i += 256) h1s[i] = 0.f;
    __syncthreads();

    const int iv   = idx[b];
    const int r_no = iv / 1512;
    const int p_no = iv - r_no * 1512;
    const float* er = e + (size_t)r_no * DTOT;
    const float* ep = e + (size_t)(NRr + p_no) * DTOT;
    for (int i = tid; i < DTOT; i += 256) {
        xs[2 + i]       = er[i];
        xs[520 + 2 + i] = ep[i];
    }
    __syncthreads();

    // ---- conv1 + leaky + avgpool2 -> h1 [16c][2r][256] (padded, tf32) ----
    {
        const int q  = tid;
        const int j0 = 2 * q;
        for (int c = 0; c < 16; ++c) {
            float W0[5], W1[5], W2[5];
            #pragma unroll
            for (int kj = 0; kj < 5; ++kj) {
                W0[kj] = w1s[c * 15 + kj];
                W1[kj] = w1s[c * 15 + 5 + kj];
                W2[kj] = w1s[c * 15 + 10 + kj];
            }
            float X0[6], X1[6];
            #pragma unroll
            for (int t = 0; t < 6; ++t) {
                X0[t] = xs[j0 + t];
                X1[t] = xs[520 + j0 + t];
            }
            const float bb = b1[c];
            float v00 = bb, v01 = bb, v10 = bb, v11 = bb;
            float v20 = bb, v21 = bb, v30 = bb, v31 = bb;
            #pragma unroll
            for (int kj = 0; kj < 5; ++kj) {
                v00 = fmaf(W2[kj], X0[kj],     v00);
                v01 = fmaf(W2[kj], X0[kj + 1], v01);
                v10 = fmaf(W1[kj], X0[kj],     v10);
                v10 = fmaf(W2[kj], X1[kj],     v10);
                v11 = fmaf(W1[kj], X0[kj + 1], v11);
                v11 = fmaf(W2[kj], X1[kj + 1], v11);
                v20 = fmaf(W0[kj], X0[kj],     v20);
                v20 = fmaf(W1[kj], X1[kj],     v20);
                v21 = fmaf(W0[kj], X0[kj + 1], v21);
                v21 = fmaf(W1[kj], X1[kj + 1], v21);
                v30 = fmaf(W0[kj], X1[kj],     v30);
                v31 = fmaf(W0[kj], X1[kj + 1], v31);
            }
            float p0 = 0.25f * (lrelu(v00) + lrelu(v01) + lrelu(v10) + lrelu(v11));
            float p1 = 0.25f * (lrelu(v20) + lrelu(v21) + lrelu(v30) + lrelu(v31));
            h1s[(c * 2 + 0) * H1W + 2 + q] = tf32r(p0);
            h1s[(c * 2 + 1) * H1W + 2 + q] = tf32r(p1);
        }
    }
    __syncthreads();

    // ---- conv2 via implicit-im2col MMA ----
    // warp w owns mtiles t = w + 8u (u=0..7): i = u>>1,
    // j0 = (u&1 ? w+8 : w)*16.  acc: 8 mtiles x 4 ntiles x 4.
    const int jl = lane >> 2;       // row within tile
    const int kq = lane & 3;
    float acc[8][4][4];
    #pragma unroll
    for (int nt = 0; nt < 4; ++nt) {
        int o = nt * 8 + 2 * (lane & 3);
        float q0 = b2[o], q1 = b2[o + 1];
        #pragma unroll
        for (int u = 0; u < 8; ++u) {
            acc[u][nt][0] = q0; acc[u][nt][1] = q1;
            acc[u][nt][2] = q0; acc[u][nt][3] = q1;
        }
    }

    for (int s = 0; s < 30; ++s) {
        const int klo = s * 8 + kq;
        const int khi = klo + 4;
        int c0 = klo / 15, t0 = klo - c0 * 15, ki0 = t0 / 5, kj0 = t0 - ki0 * 5;
        int c1 = khi / 15, t1 = khi - c1 * 15, ki1 = t1 / 5, kj1 = t1 - ki1 * 5;
        int bl[4], bh[4];
        #pragma unroll
        for (int i = 0; i < 4; ++i) {
            int r0 = i + ki0 - 2;
            bl[i] = (((unsigned)r0 < 2u) ? (c0 * 2 + r0) * H1W : 32 * H1W) + kj0;
            int r1 = i + ki1 - 2;
            bh[i] = (((unsigned)r1 < 2u) ? (c1 * 2 + r1) * H1W : 32 * H1W) + kj1;
        }
        uint32_t bq[4][2];
        #pragma unroll
        for (int nt = 0; nt < 4; ++nt) {
            int o = nt * 8 + (lane >> 2);
            bq[nt][0] = w2u[o * W2S + klo];
            bq[nt][1] = w2u[o * W2S + khi];
        }
        #pragma unroll
        for (int u = 0; u < 8; ++u) {
            int i   = u >> 1;
            int col = (((u & 1) ? w + 8 : w) << 4) + jl;
            uint32_t a[4];
            a[0] = h1u[bl[i] + col];
            a[1] = h1u[bl[i] + col + 8];
            a[2] = h1u[bh[i] + col];
            a[3] = h1u[bh[i] + col + 8];
            #pragma unroll
            for (int nt = 0; nt < 4; ++nt)
                mma8(acc[u][nt], a, bq[nt]);
        }
    }

    // ---- lrelu + maxpool (j via shfl, i via regs) + tanh -> pool smem ----
    const bool act = ((lane >> 2) & 1) == 0;
    const int jp = lane >> 3;
    #pragma unroll
    for (int uu = 0; uu < 4; ++uu) {
        int u  = (uu & 1) + (uu >> 1) * 4;     // {0,1,4,5}
        int ip = (u >= 4);
        int jb = (((u & 1) ? w + 8 : w) << 3);
        #pragma unroll
        for (int nt = 0; nt < 4; ++nt) {
            int o = nt * 8 + 2 * (lane & 3);
            float v[4];
            #pragma unroll
            for (int q = 0; q < 4; ++q) {
                float x = lrelu(acc[u][nt][q]);
                float y = lrelu(acc[u + 2][nt][q]);
                x = fmaxf(x, y);                               // i-pool
                float z = __shfl_xor_sync(0xffffffffu, x, 4);  // j-pool
                v[q] = fmaxf(x, z);
            }
            if (act) {
                int base  = (ip * 128 + jb + jp) * 33;
                int base2 = base + 4 * 33;
                pool[base  + o]     = tanhf(v[0]);
                pool[base  + o + 1] = tanhf(v[1]);
                pool[base2 + o]     = tanhf(v[2]);
                pool[base2 + o + 1] = tanhf(v[3]);
            }
        }
    }
    __syncthreads();

    // ---- coalesced flat write + fused output dot ----
    float d0 = 0.f, d1 = 0.f;
    float* fb = flat + (size_t)b * FLATN;
    const float2* Wo2 = (const float2*)Wout;
    #pragma unroll
    for (int g = 0; g < 32; ++g) {
        float v = pool[tid * 33 + g];
        int k = g * 256 + tid;
        fb[k] = v;
        float2 wv = __ldg(Wo2 + k);
        d0 = fmaf(v, wv.x, d0);
        d1 = fmaf(v, wv.y, d1);
    }
    #pragma unroll
    for (int off = 16; off > 0; off >>= 1) {
        d0 += __shfl_down_sync(0xffffffffu, d0, off);
        d1 += __shfl_down_sync(0xffffffffu, d1, off);
    }
    if (lane == 0) { red[w * 2] = d0; red[w * 2 + 1] = d1; }
    __syncthreads();
    if (tid == 0) {
        float s0 = 0.f, s1 = 0.f;
        #pragma unroll
        for (int i = 0; i < 8; ++i) { s0 += red[i * 2]; s1 += red[i * 2 + 1]; }
        outp[(size_t)b * 2 + 0] = s0 + bout[0];
        outp[(size_t)b * 2 + 1] = s1 + bout[1];
    }
}

// ---------------------------------------------------------------------------
// kernel_launch
// ---------------------------------------------------------------------------
extern "C" void kernel_launch(void* const* d_in, const int* in_sizes, int n_in,
                              void* d_out, int out_size)
{
    const float* r_att   = (const float*)d_in[0];
    const float* p_att   = (const float*)d_in[1];
    const float* r_fun   = (const float*)d_in[2];
    const float* p_fun   = (const float*)d_in[3];
    const int*   idx     = (const int*)  d_in[4];
    const float* b_att1  = (const float*)d_in[6];
    const float* b_att2  = (const float*)d_in[8];
    const float* b_fun1  = (const float*)d_in[10];
    const float* b_fun2  = (const float*)d_in[12];
    const float* conv1_w = (const float*)d_in[13];
    const float* conv1_b = (const float*)d_in[14];
    const float* conv2_w = (const float*)d_in[15];
    const float* conv2_b = (const float*)d_in[16];
    const float* W_out   = (const float*)d_in[17];
    const float* b_out   = (const float*)d_in[18];
    const float* W_att1  = (const float*)d_in[5];
    const float* W_att2  = (const float*)d_in[7];
    const float* W_fun1  = (const float*)d_in[9];
    const float* W_fun2  = (const float*)d_in[11];

    float* out  = (float*)d_out;
    float* e    = out;
    float* outp = out + (size_t)NTOT * DTOT;
    float* flat = outp + (size_t)BATCH * 2;

    float* hatt = nullptr; cudaGetSymbolAddress((void**)&hatt, g_h_att);
    float* hfun = nullptr; cudaGetSymbolAddress((void**)&hfun, g_h_fun);
    float* aatt = nullptr; cudaGetSymbolAddress((void**)&aatt, g_aatt);
    float* afun = nullptr; cudaGetSymbolAddress((void**)&afun, g_afun);
    float* w1a  = nullptr; cudaGetSymbolAddress((void**)&w1a,  g_w1a);
    float* w1f  = nullptr; cudaGetSymbolAddress((void**)&w1f,  g_w1f);
    float* w2a  = nullptr; cudaGetSymbolAddress((void**)&w2a,  g_w2a);
    float* w2f  = nullptr; cudaGetSymbolAddress((void**)&w2f,  g_w2f);

    auto launch_rc = [](float* dst, const float* src, size_t n) {
        int n4 = (int)(n / 4);
        rc4<<<(n4 + 255) / 256, 256>>>((float4*)dst, (const float4*)src, n4);
    };

    // prepass: tf32-rounded copies
    launch_rc(aatt, r_att, (size_t)NRr * KATT);
    launch_rc(aatt + (size_t)NRr * KATT, p_att, (size_t)NPp * KATT);
    pad_fun<<<dim3((KFP + 1023) / 1024, NTOT), 1024>>>(r_fun, p_fun);
    launch_rc(w1a, W_att1, (size_t)KATT * 2048);
    launch_rc(w1f, W_fun1, (size_t)KFUN * 4096);
    launch_rc(w2a, W_att2, (size_t)2048 * 256);
    launch_rc(w2f, W_fun2, (size_t)4096 * 256);

    // GEMMs
    const int smA128 = (3 * 128 * 20 + 3 * 16 * 136) * 4;   // 56832
    const int smA64  = (3 * 64 * 20  + 3 * 16 * 136) * 4;   // 41472
    cudaFuncSetAttribute(mma_gemm<128, 0, 1>,
                         cudaFuncAttributeMaxDynamicSharedMemorySize, smA128);
    cudaFuncSetAttribute(mma_gemm<64, 1, 0>,
                         cudaFuncAttributeMaxDynamicSharedMemorySize, smA64);

    mma_gemm<128, 0, 1><<<dim3(2048 / 128, (NTOT + 127) / 128), 256, smA128>>>(
        aatt, aatt, NTOT, KATT, NTOT, 2048, KATT, KATT, w1a, b_att1, hatt, 2048, 0);
    mma_gemm<128, 0, 1><<<dim3(4096 / 128, (NTOT + 127) / 128), 256, smA128>>>(
        afun, afun, NTOT, KFP, NTOT, 4096, KFUN, KFP, w1f, b_fun1, hfun, 4096, 0);
    mma_gemm<64, 1, 0><<<dim3(256 / 128, (NTOT + 63) / 64), 256, smA64>>>(
        hatt, hatt, NTOT, 2048, NTOT, 256, 2048, 2048, w2a, b_att2, e, DTOT, 0);
    mma_gemm<64, 1, 0><<<dim3(256 / 128, (NTOT + 63) / 64), 256, smA64>>>(
        hfun, hfun, NTOT, 4096, NTOT, 256, 4096, 4096, w2f, b_fun2, e, DTOT, 256);

    // fused conv head
    const int smC = 26132 * 4;   // 104528 B
    cudaFuncSetAttribute(conv_head,
                         cudaFuncAttributeMaxDynamicSharedMemorySize, smC);
    conv_head<<<BATCH, 256, smC>>>(
        e, idx, conv1_w, conv1_b, conv2_w, conv2_b, W_out, b_out, outp, flat);
}

// round 4
// speedup vs baseline: 3.4219x; 1.0603x over previous
#include <cuda_runtime.h>
#include <cstdint>

// ---------------------------------------------------------------------------
// Problem constants
// ---------------------------------------------------------------------------
#define NRr     2000
#define NPp     1512
#define NTOT    3512          // NRr + NPp
#define DTOT    512           // ATT(256) + FUN(256)
#define BATCH   8192
#define FLATN   8192          // 32*2*128
#define KATT    3000
#define KFUN    5603
#define KFP     5604          // padded (multiple of 4)

// Scratch (device globals: allocation is forbidden)
__device__ float g_h_att[(size_t)NTOT * 2048];
__device__ float g_h_fun[(size_t)NTOT * 4096];
__device__ float g_aatt [(size_t)NTOT * KATT];
__device__ float g_afun [(size_t)NTOT * KFP];
__device__ float g_w1a  [(size_t)KATT * 2048];
__device__ float g_w1f  [(size_t)KFUN * 4096];
__device__ float g_w2a  [(size_t)2048 * 256];
__device__ float g_w2f  [(size_t)4096 * 256];

// ---------------------------------------------------------------------------
// helpers
// ---------------------------------------------------------------------------
__device__ __forceinline__ uint32_t f2tf32(float f) {
    uint32_t r;
    asm("cvt.rna.tf32.f32 %0, %1;" : "=r"(r) : "f"(f));
    return r;
}
__device__ __forceinline__ float tf32r(float f) {
    return __uint_as_float(f2tf32(f));
}
__device__ __forceinline__ float tanh_fast(float x) {
    float r;
    asm("tanh.approx.f32 %0, %1;" : "=f"(r) : "f"(x));
    return r;
}

__device__ __forceinline__ void mma8(float* d, const uint32_t* a, const uint32_t* b) {
    asm volatile(
        "mma.sync.aligned.m16n8k8.row.col.f32.tf32.tf32.f32 "
        "{%0,%1,%2,%3},{%4,%5,%6,%7},{%8,%9},{%0,%1,%2,%3};"
        : "+f"(d[0]), "+f"(d[1]), "+f"(d[2]), "+f"(d[3])
        : "r"(a[0]), "r"(a[1]), "r"(a[2]), "r"(a[3]), "r"(b[0]), "r"(b[1]));
}

__device__ __forceinline__ void cpa16(float* smem_dst, const float* g, bool pred) {
    uint32_t s = (uint32_t)__cvta_generic_to_shared(smem_dst);
    int sz = pred ? 16 : 0;
    asm volatile("cp.async.cg.shared.global [%0], [%1], 16, %2;"
                 :: "r"(s), "l"(g), "r"(sz));
}

__device__ __forceinline__ float lrelu(float v) {
    return v >= 0.f ? v : 0.01f * v;
}

// ---------------------------------------------------------------------------
// Prepass: round-to-tf32 copies (so GEMM inner loops need no cvt)
// ---------------------------------------------------------------------------
__global__ void rc4(float4* __restrict__ dst, const float4* __restrict__ src, int n4) {
    int i = blockIdx.x * blockDim.x + threadIdx.x;
    if (i < n4) {
        float4 v = src[i];
        v.x = tf32r(v.x); v.y = tf32r(v.y); v.z = tf32r(v.z); v.w = tf32r(v.w);
        dst[i] = v;
    }
}

__global__ void pad_fun(const float* __restrict__ r, const float* __restrict__ p) {
    int row = blockIdx.y;
    const float* src = (row < NRr) ? (r + (size_t)row * KFUN)
                                   : (p + (size_t)(row - NRr) * KFUN);
    float* dst = g_afun + (size_t)row * KFP;
    int c = blockIdx.x * blockDim.x + threadIdx.x;
    if (c < KFP) dst[c] = (c < KFUN) ? tf32r(src[c]) : 0.f;
}

// ---------------------------------------------------------------------------
// TF32 tensor-core GEMM, 3-stage cp.async pipeline.
// ---------------------------------------------------------------------------
template<int BM, int ACT, int ROUND>
__global__ __launch_bounds__(256, 2)
void mma_gemm(const float* __restrict__ A1, const float* __restrict__ A2,
              int splitM, int lda, int M, int N, int K, int KA,
              const float* __restrict__ B, const float* __restrict__ bias,
              float* __restrict__ C, int ldc, int coloff)
{
    constexpr int BN = 128, BK = 16, ST = 3;
    constexpr int AS = 20;
    constexpr int BS = 136;
    constexpr int WM = BM / 4;
    constexpr int MI = WM / 16;
    constexpr int ASZ = BM * AS;
    constexpr int BSZ = BK * BS;

    extern __shared__ float dsm[];
    float* As = dsm;
    float* Bs = dsm + ST * ASZ;

    const int tid  = threadIdx.x;
    const int lane = tid & 31, warp = tid >> 5;
    const int wm = warp >> 1, wn = warp & 1;
    const int bm = blockIdx.y * BM, bn = blockIdx.x * BN;

    int ar, ak;
    if (BM == 128) { ar = tid >> 1; ak = (tid & 1) * 8; }
    else           { ar = tid >> 2; ak = (tid & 3) * 4; }
    const int am  = bm + ar;
    const bool amv = (am < M);
    const float* arow;
    {
        int mc = amv ? am : 0;
        arow = (mc < splitM) ? (A1 + (size_t)mc * lda)
                             : (A2 + (size_t)(mc - splitM) * lda);
    }
    const int bk = tid >> 5;
    const int bc = (tid & 31) * 4;

    float acc[MI][8][4];
    #pragma unroll
    for (int i = 0; i < MI; ++i)
        #pragma unroll
        for (int j = 0; j < 8; ++j)
            #pragma unroll
            for (int q = 0; q < 4; ++q) acc[i][j][q] = 0.f;

    const int nIt = (K + BK - 1) / BK;

    auto load_stage = [&](int st, int kt) {
        float* as = As + st * ASZ;
        float* bs = Bs + st * BSZ;
        if (BM == 128) {
            #pragma unroll
            for (int u = 0; u < 2; ++u) {
                int k = kt + ak + u * 4;
                bool p = amv && (k < KA);
                cpa16(&as[ar * AS + ak + u * 4], p ? (arow + k) : A1, p);
            }
        } else {
            int k = kt + ak;
            bool p = amv && (k < KA);
            cpa16(&as[ar * AS + ak], p ? (arow + k) : A1, p);
        }
        #pragma unroll
        for (int u = 0; u < 2; ++u) {
            int k = kt + bk + u * 8;
            bool p = (k < K);
            cpa16(&bs[(bk + u * 8) * BS + bc],
                  p ? (B + (size_t)k * N + bn + bc) : B, p);
        }
        asm volatile("cp.async.commit_group;");
    };

    load_stage(0, 0);
    load_stage(1, BK);

    for (int it = 0; it < nIt; ++it) {
        const int cur = it % ST;
        asm volatile("cp.async.wait_group 1;");
        __syncthreads();

        int nx = it + ST - 1;
        if (nx < nIt) load_stage(nx % ST, nx * BK);
        else          asm volatile("cp.async.commit_group;");

        const uint32_t* asu = (const uint32_t*)(As + cur * ASZ);
        const uint32_t* bsu = (const uint32_t*)(Bs + cur * BSZ);
        #pragma unroll
        for (int kk = 0; kk < BK; kk += 8) {
            uint32_t af[MI][4];
            #pragma unroll
            for (int mi = 0; mi < MI; ++mi) {
                int r0 = wm * WM + mi * 16 + (lane >> 2);
                int c0 = kk + (lane & 3);
                af[mi][0] = asu[ r0      * AS + c0    ];
                af[mi][1] = asu[(r0 + 8) * AS + c0    ];
                af[mi][2] = asu[ r0      * AS + c0 + 4];
                af[mi][3] = asu[(r0 + 8) * AS + c0 + 4];
            }
            uint32_t bf[8][2];
            #pragma unroll
            for (int ni = 0; ni < 8; ++ni) {
                int c = wn * 64 + ni * 8 + (lane >> 2);
                bf[ni][0] = bsu[(kk + (lane & 3)    ) * BS + c];
                bf[ni][1] = bsu[(kk + (lane & 3) + 4) * BS + c];
            }
            #pragma unroll
            for (int mi = 0; mi < MI; ++mi)
                #pragma unroll
                for (int ni = 0; ni < 8; ++ni)
                    mma8(acc[mi][ni], af[mi], bf[ni]);
        }
        __syncthreads();
    }

    #pragma unroll
    for (int mi = 0; mi < MI; ++mi) {
        #pragma unroll
        for (int ni = 0; ni < 8; ++ni) {
            int m0 = bm + wm * WM + mi * 16 + (lane >> 2);
            int n  = bn + wn * 64 + ni * 8 + (lane & 3) * 2;
            float bi0 = bias[n], bi1 = bias[n + 1];
            #pragma unroll
            for (int h = 0; h < 2; ++h) {
                int m = m0 + h * 8;
                if (m < M) {
                    float v0 = acc[mi][ni][h * 2 + 0] + bi0;
                    float v1 = acc[mi][ni][h * 2 + 1] + bi1;
                    if (ACT == 0) {
                        v0 = 0.5f * v0 * (1.f + erff(v0 * 0.70710678118654752f));
                        v1 = 0.5f * v1 * (1.f + erff(v1 * 0.70710678118654752f));
                    } else {
                        v0 = 1.f / (1.f + __expf(-v0));
                        v1 = 1.f / (1.f + __expf(-v1));
                    }
                    if (ROUND) { v0 = tf32r(v0); v1 = tf32r(v1); }
                    *(float2*)&C[(size_t)m * ldc + coloff + n] = make_float2(v0, v1);
                }
            }
        }
    }
}

// ---------------------------------------------------------------------------
// Fused conv head (R3 structure; tanh.approx)
// ---------------------------------------------------------------------------
#define W2S 244
#define H1W 260

__global__ __launch_bounds__(256)
void conv_head(const float* __restrict__ e,
               const int* __restrict__ idx,
               const float* __restrict__ w1, const float* __restrict__ b1,
               const float* __restrict__ w2, const float* __restrict__ b2,
               const float* __restrict__ Wout, const float* __restrict__ bout,
               float* __restrict__ outp,
               float* __restrict__ flat)
{
    extern __shared__ float sm[];
    float* w1s  = sm;                 // 240
    float* w2s  = sm + 240;           // 32*244
    float* xs   = sm + 8048;          // 1040
    float* h1s  = sm + 9088;          // 33*260 (row 32 = zero row)
    float* pool = sm + 17668;         // 256*33
    float* red  = sm + 26116;         // 16
    const uint32_t* h1u = (const uint32_t*)h1s;
    const uint32_t* w2u = (const uint32_t*)w2s;

    const int tid = threadIdx.x;
    const int lane = tid & 31, w = tid >> 5;
    const int b = blockIdx.x;

    for (int i = tid; i < 240; i += 256) w1s[i] = w1[i];
    for (int i = tid; i < 7680; i += 256) {
        int o = i / 240, k = i - o * 240;
        w2s[o * W2S + k] = tf32r(w2[i]);
    }
    for (int i = tid; i < 1040; i += 256) xs[i] = 0.f;
    for (int i = tid; i < 8580; i += 256) h1s[i] = 0.f;
    __syncthreads();

    const int iv   = idx[b];
    const int r_no = iv / 1512;
    const int p_no = iv - r_no * 1512;
    const float* er = e + (size_t)r_no * DTOT;
    const float* ep = e + (size_t)(NRr + p_no) * DTOT;
    for (int i = tid; i < DTOT; i += 256) {
        xs[2 + i]       = er[i];
        xs[520 + 2 + i] = ep[i];
    }
    __syncthreads();

    // conv1 + leaky + avgpool2 -> h1 (tf32)
    {
        const int q  = tid;
        const int j0 = 2 * q;
        for (int c = 0; c < 16; ++c) {
            float W0[5], W1[5], W2[5];
            #pragma unroll
            for (int kj = 0; kj < 5; ++kj) {
                W0[kj] = w1s[c * 15 + kj];
                W1[kj] = w1s[c * 15 + 5 + kj];
                W2[kj] = w1s[c * 15 + 10 + kj];
            }
            float X0[6], X1[6];
            #pragma unroll
            for (int t = 0; t < 6; ++t) {
                X0[t] = xs[j0 + t];
                X1[t] = xs[520 + j0 + t];
            }
            const float bb = b1[c];
            float v00 = bb, v01 = bb, v10 = bb, v11 = bb;
            float v20 = bb, v21 = bb, v30 = bb, v31 = bb;
            #pragma unroll
            for (int kj = 0; kj < 5; ++kj) {
                v00 = fmaf(W2[kj], X0[kj],     v00);
                v01 = fmaf(W2[kj], X0[kj + 1], v01);
                v10 = fmaf(W1[kj], X0[kj],     v10);
                v10 = fmaf(W2[kj], X1[kj],     v10);
                v11 = fmaf(W1[kj], X0[kj + 1], v11);
                v11 = fmaf(W2[kj], X1[kj + 1], v11);
                v20 = fmaf(W0[kj], X0[kj],     v20);
                v20 = fmaf(W1[kj], X1[kj],     v20);
                v21 = fmaf(W0[kj], X0[kj + 1], v21);
                v21 = fmaf(W1[kj], X1[kj + 1], v21);
                v30 = fmaf(W0[kj], X1[kj],     v30);
                v31 = fmaf(W0[kj], X1[kj + 1], v31);
            }
            float p0 = 0.25f * (lrelu(v00) + lrelu(v01) + lrelu(v10) + lrelu(v11));
            float p1 = 0.25f * (lrelu(v20) + lrelu(v21) + lrelu(v30) + lrelu(v31));
            h1s[(c * 2 + 0) * H1W + 2 + q] = tf32r(p0);
            h1s[(c * 2 + 1) * H1W + 2 + q] = tf32r(p1);
        }
    }
    __syncthreads();

    // conv2 via implicit-im2col MMA
    const int jl = lane >> 2;
    const int kq = lane & 3;
    float acc[8][4][4];
    #pragma unroll
    for (int nt = 0; nt < 4; ++nt) {
        int o = nt * 8 + 2 * (lane & 3);
        float q0 = b2[o], q1 = b2[o + 1];
        #pragma unroll
        for (int u = 0; u < 8; ++u) {
            acc[u][nt][0] = q0; acc[u][nt][1] = q1;
            acc[u][nt][2] = q0; acc[u][nt][3] = q1;
        }
    }

    for (int s = 0; s < 30; ++s) {
        const int klo = s * 8 + kq;
        const int khi = klo + 4;
        int c0 = klo / 15, t0 = klo - c0 * 15, ki0 = t0 / 5, kj0 = t0 - ki0 * 5;
        int c1 = khi / 15, t1 = khi - c1 * 15, ki1 = t1 / 5, kj1 = t1 - ki1 * 5;
        int bl[4], bh[4];
        #pragma unroll
        for (int i = 0; i < 4; ++i) {
            int r0 = i + ki0 - 2;
            bl[i] = (((unsigned)r0 < 2u) ? (c0 * 2 + r0) * H1W : 32 * H1W) + kj0;
            int r1 = i + ki1 - 2;
            bh[i] = (((unsigned)r1 < 2u) ? (c1 * 2 + r1) * H1W : 32 * H1W) + kj1;
        }
        uint32_t bq[4][2];
        #pragma unroll
        for (int nt = 0; nt < 4; ++nt) {
            int o = nt * 8 + (lane >> 2);
            bq[nt][0] = w2u[o * W2S + klo];
            bq[nt][1] = w2u[o * W2S + khi];
        }
        #pragma unroll
        for (int u = 0; u < 8; ++u) {
            int i   = u >> 1;
            int col = (((u & 1) ? w + 8 : w) << 4) + jl;
            uint32_t a[4];
            a[0] = h1u[bl[i] + col];
            a[1] = h1u[bl[i] + col + 8];
            a[2] = h1u[bh[i] + col];
            a[3] = h1u[bh[i] + col + 8];
            #pragma unroll
            for (int nt = 0; nt < 4; ++nt)
                mma8(acc[u][nt], a, bq[nt]);
        }
    }

    // lrelu + maxpool + tanh.approx -> pool smem
    const bool act = ((lane >> 2) & 1) == 0;
    const int jp = lane >> 3;
    #pragma unroll
    for (int uu = 0; uu < 4; ++uu) {
        int u  = (uu & 1) + (uu >> 1) * 4;     // {0,1,4,5}
        int ip = (u >= 4);
        int jb = (((u & 1) ? w + 8 : w) << 3);
        #pragma unroll
        for (int nt = 0; nt < 4; ++nt) {
            int o = nt * 8 + 2 * (lane & 3);
            float v[4];
            #pragma unroll
            for (int q = 0; q < 4; ++q) {
                float x = lrelu(acc[u][nt][q]);
                float y = lrelu(acc[u + 2][nt][q]);
                x = fmaxf(x, y);
                float z = __shfl_xor_sync(0xffffffffu, x, 4);
                v[q] = fmaxf(x, z);
            }
            if (act) {
                int base  = (ip * 128 + jb + jp) * 33;
                int base2 = base + 4 * 33;
                pool[base  + o]     = tanh_fast(v[0]);
                pool[base  + o + 1] = tanh_fast(v[1]);
                pool[base2 + o]     = tanh_fast(v[2]);
                pool[base2 + o + 1] = tanh_fast(v[3]);
            }
        }
    }
    __syncthreads();

    // coalesced flat write + fused output dot
    float d0 = 0.f, d1 = 0.f;
    float* fb = flat + (size_t)b * FLATN;
    const float2* Wo2 = (const float2*)Wout;
    #pragma unroll
    for (int g = 0; g < 32; ++g) {
        float v = pool[tid * 33 + g];
        int k = g * 256 + tid;
        fb[k] = v;
        float2 wv = __ldg(Wo2 + k);
        d0 = fmaf(v, wv.x, d0);
        d1 = fmaf(v, wv.y, d1);
    }
    #pragma unroll
    for (int off = 16; off > 0; off >>= 1) {
        d0 += __shfl_down_sync(0xffffffffu, d0, off);
        d1 += __shfl_down_sync(0xffffffffu, d1, off);
    }
    if (lane == 0) { red[w * 2] = d0; red[w * 2 + 1] = d1; }
    __syncthreads();
    if (tid == 0) {
        float s0 = 0.f, s1 = 0.f;
        #pragma unroll
        for (int i = 0; i < 8; ++i) { s0 += red[i * 2]; s1 += red[i * 2 + 1]; }
        outp[(size_t)b * 2 + 0] = s0 + bout[0];
        outp[(size_t)b * 2 + 1] = s1 + bout[1];
    }
}

// ---------------------------------------------------------------------------
// kernel_launch — fork att chain onto a side stream, join before conv_head
// ---------------------------------------------------------------------------
extern "C" void kernel_launch(void* const* d_in, const int* in_sizes, int n_in,
                              void* d_out, int out_size)
{
    const float* r_att   = (const float*)d_in[0];
    const float* p_att   = (const float*)d_in[1];
    const float* r_fun   = (const float*)d_in[2];
    const float* p_fun   = (const float*)d_in[3];
    const int*   idx     = (const int*)  d_in[4];
    const float* W_att1  = (const float*)d_in[5];
    const float* b_att1  = (const float*)d_in[6];
    const float* W_att2  = (const float*)d_in[7];
    const float* b_att2  = (const float*)d_in[8];
    const float* W_fun1  = (const float*)d_in[9];
    const float* b_fun1  = (const float*)d_in[10];
    const float* W_fun2  = (const float*)d_in[11];
    const float* b_fun2  = (const float*)d_in[12];
    const float* conv1_w = (const float*)d_in[13];
    const float* conv1_b = (const float*)d_in[14];
    const float* conv2_w = (const float*)d_in[15];
    const float* conv2_b = (const float*)d_in[16];
    const float* W_out   = (const float*)d_in[17];
    const float* b_out   = (const float*)d_in[18];

    float* out  = (float*)d_out;
    float* e    = out;
    float* outp = out + (size_t)NTOT * DTOT;
    float* flat = outp + (size_t)BATCH * 2;

    float* hatt = nullptr; cudaGetSymbolAddress((void**)&hatt, g_h_att);
    float* hfun = nullptr; cudaGetSymbolAddress((void**)&hfun, g_h_fun);
    float* aatt = nullptr; cudaGetSymbolAddress((void**)&aatt, g_aatt);
    float* afun = nullptr; cudaGetSymbolAddress((void**)&afun, g_afun);
    float* w1a  = nullptr; cudaGetSymbolAddress((void**)&w1a,  g_w1a);
    float* w1f  = nullptr; cudaGetSymbolAddress((void**)&w1f,  g_w1f);
    float* w2a  = nullptr; cudaGetSymbolAddress((void**)&w2a,  g_w2a);
    float* w2f  = nullptr; cudaGetSymbolAddress((void**)&w2f,  g_w2f);

    // side stream + events, created once on the (uncaptured) correctness call
    static cudaStream_t s_att = nullptr;
    static cudaEvent_t  ev0 = nullptr, evA = nullptr;
    if (!s_att) {
        cudaStreamCreateWithFlags(&s_att, cudaStreamNonBlocking);
        cudaEventCreateWithFlags(&ev0, cudaEventDisableTiming);
        cudaEventCreateWithFlags(&evA, cudaEventDisableTiming);
    }

    auto launch_rc = [](float* dst, const float* src, size_t n, cudaStream_t st) {
        int n4 = (int)(n / 4);
        rc4<<<(n4 + 255) / 256, 256, 0, st>>>((float4*)dst, (const float4*)src, n4);
    };

    const int smA128 = (3 * 128 * 20 + 3 * 16 * 136) * 4;   // 56832
    const int smA64  = (3 * 64 * 20  + 3 * 16 * 136) * 4;   // 41472
    cudaFuncSetAttribute(mma_gemm<128, 0, 1>,
                         cudaFuncAttributeMaxDynamicSharedMemorySize, smA128);
    cudaFuncSetAttribute(mma_gemm<64, 1, 0>,
                         cudaFuncAttributeMaxDynamicSharedMemorySize, smA64);
    const int smC = 26132 * 4;
    cudaFuncSetAttribute(conv_head,
                         cudaFuncAttributeMaxDynamicSharedMemorySize, smC);

    // fork
    cudaEventRecord(ev0, 0);
    cudaStreamWaitEvent(s_att, ev0, 0);

    // att chain on side stream
    launch_rc(aatt, r_att, (size_t)NRr * KATT, s_att);
    launch_rc(aatt + (size_t)NRr * KATT, p_att, (size_t)NPp * KATT, s_att);
    launch_rc(w1a, W_att1, (size_t)KATT * 2048, s_att);
    launch_rc(w2a, W_att2, (size_t)2048 * 256, s_att);
    mma_gemm<128, 0, 1><<<dim3(2048 / 128, (NTOT + 127) / 128), 256, smA128, s_att>>>(
        aatt, aatt, NTOT, KATT, NTOT, 2048, KATT, KATT, w1a, b_att1, hatt, 2048, 0);
    mma_gemm<64, 1, 0><<<dim3(256 / 128, (NTOT + 63) / 64), 256, smA64, s_att>>>(
        hatt, hatt, NTOT, 2048, NTOT, 256, 2048, 2048, w2a, b_att2, e, DTOT, 0);
    cudaEventRecord(evA, s_att);

    // fun chain on main stream
    pad_fun<<<dim3((KFP + 1023) / 1024, NTOT), 1024>>>(r_fun, p_fun);
    launch_rc(w1f, W_fun1, (size_t)KFUN * 4096, 0);
    launch_rc(w2f, W_fun2, (size_t)4096 * 256, 0);
    mma_gemm<128, 0, 1><<<dim3(4096 / 128, (NTOT + 127) / 128), 256, smA128>>>(
        afun, afun, NTOT, KFP, NTOT, 4096, KFUN, KFP, w1f, b_fun1, hfun, 4096, 0);
    mma_gemm<64, 1, 0><<<dim3(256 / 128, (NTOT + 63) / 64), 256, smA64>>>(
        hfun, hfun, NTOT, 4096, NTOT, 256, 4096, 4096, w2f, b_fun2, e, DTOT, 256);

    // join, then conv head
    cudaStreamWaitEvent(0, evA, 0);
    conv_head<<<BATCH, 256, smC>>>(
        e, idx, conv1_w, conv1_b, conv2_w, conv2_b, W_out, b_out, outp, flat);
}

// round 5
// speedup vs baseline: 4.7093x; 1.3763x over previous
#include <cuda_runtime.h>
#include <cuda_fp16.h>
#include <cstdint>

// ---------------------------------------------------------------------------
// Problem constants
// ---------------------------------------------------------------------------
#define NRr     2000
#define NPp     1512
#define NTOT    3512
#define DTOT    512
#define BATCH   8192
#define FLATN   8192
#define KATT    3000
#define KATT_T  3008          // padded to /32
#define KFUN    5603
#define KFUN_T  5632          // padded to /32

// Scratch (device globals; allocation is forbidden)
__device__ __half g_ah_att[(size_t)NTOT * KATT_T];
__device__ __half g_ah_fun[(size_t)NTOT * KFUN_T];
__device__ __half g_wt1a [(size_t)2048 * KATT_T];
__device__ __half g_wt1f [(size_t)4096 * KFUN_T];
__device__ __half g_wt2a [(size_t)256 * 2048];
__device__ __half g_wt2f [(size_t)256 * 4096];
__device__ __half g_h_att[(size_t)NTOT * 2048];
__device__ __half g_h_fun[(size_t)NTOT * 4096];

// ---------------------------------------------------------------------------
// helpers
// ---------------------------------------------------------------------------
__device__ __forceinline__ float tanh_fast(float x) {
    float r;
    asm("tanh.approx.f32 %0, %1;" : "=f"(r) : "f"(x));
    return r;
}

__device__ __forceinline__ void mma16(float* d, const uint32_t* a, const uint32_t* b) {
    asm volatile(
        "mma.sync.aligned.m16n8k16.row.col.f32.f16.f16.f32 "
        "{%0,%1,%2,%3},{%4,%5,%6,%7},{%8,%9},{%0,%1,%2,%3};"
        : "+f"(d[0]), "+f"(d[1]), "+f"(d[2]), "+f"(d[3])
        : "r"(a[0]), "r"(a[1]), "r"(a[2]), "r"(a[3]), "r"(b[0]), "r"(b[1]));
}

__device__ __forceinline__ void cpa16h(__half* smem_dst, const __half* g, bool pred) {
    uint32_t s = (uint32_t)__cvta_generic_to_shared(smem_dst);
    int sz = pred ? 16 : 0;
    asm volatile("cp.async.cg.shared.global [%0], [%1], 16, %2;"
                 :: "r"(s), "l"(g), "r"(sz));
}

__device__ __forceinline__ float lrelu(float v) {
    return v >= 0.f ? v : 0.01f * v;
}

// ---------------------------------------------------------------------------
// Prepass 1: activations fp32 -> half, rows from r (first nr) then p, K padded
// ---------------------------------------------------------------------------
__global__ void cvtA(const float* __restrict__ r, const float* __restrict__ p,
                     int nr, int Kin, __half* __restrict__ dst, int KT)
{
    int row = blockIdx.y;
    int c = blockIdx.x * 256 + threadIdx.x;
    if (c >= KT) return;
    const float* s = (row < nr) ? (r + (size_t)row * Kin)
                                : (p + (size_t)(row - nr) * Kin);
    dst[(size_t)row * KT + c] = (c < Kin) ? __float2half_rn(s[c]) : __half(0.f);
}

// ---------------------------------------------------------------------------
// Prepass 2: W [K][N] fp32 -> WT [N][KT] half (zero pad k >= K). N % 32 == 0.
// ---------------------------------------------------------------------------
__global__ void transpose_h(const float* __restrict__ W, __half* __restrict__ WT,
                            int K, int N, int KT)
{
    __shared__ float t[32][33];
    int k0 = blockIdx.y * 32, n0 = blockIdx.x * 32;
    #pragma unroll
    for (int r = threadIdx.y; r < 32; r += 8) {
        int k = k0 + r;
        t[r][threadIdx.x] = (k < K) ? W[(size_t)k * N + n0 + threadIdx.x] : 0.f;
    }
    __syncthreads();
    #pragma unroll
    for (int r = threadIdx.y; r < 32; r += 8) {
        int n = n0 + r, k = k0 + threadIdx.x;
        WT[(size_t)n * KT + k] = __float2half_rn(t[threadIdx.x][r]);
    }
}

// ---------------------------------------------------------------------------
// FP16 tensor-core GEMM (m16n8k16), 3-stage cp.async pipeline.
// C[m, coloff+n] = act(sum_k A[m,k]*BT[n,k] + bias[n])
// A: half [M][lda] (zero-padded to KT), BT: half [N][ldb] (k-major, padded).
// KT % 32 == 0, N % 128 == 0. 256 threads, warps 4x2, warp tile (BM/4) x 64.
// ACT: 0 gelu, 1 sigmoid.  OUTF: 0 -> half output, 1 -> float output.
// ---------------------------------------------------------------------------
template<int BM, int ACT, int OUTF>
__global__ __launch_bounds__(256, 2)
void gemm_h(const __half* __restrict__ A, int lda, int M, int N, int KT,
            const __half* __restrict__ BT, int ldb,
            const float* __restrict__ bias,
            void* __restrict__ Cv, int ldc, int coloff)
{
    constexpr int ST = 3;
    constexpr int WM = BM / 4;
    constexpr int MI = WM / 16;
    constexpr int ASZ = BM * 40;     // halves
    constexpr int BSZ = 128 * 40;    // halves

    extern __shared__ __half hsm[];
    __half* Ash = hsm;
    __half* Bsh = hsm + ST * ASZ;

    const int tid  = threadIdx.x;
    const int lane = tid & 31, warp = tid >> 5;
    const int wm = warp >> 1, wn = warp & 1;
    const int bm = blockIdx.y * BM, bn = blockIdx.x * 128;

    float acc[MI][8][4];
    #pragma unroll
    for (int i = 0; i < MI; ++i)
        #pragma unroll
        for (int j = 0; j < 8; ++j)
            #pragma unroll
            for (int q = 0; q < 4; ++q) acc[i][j][q] = 0.f;

    const int nIt = KT / 32;
    const int arr = tid >> 2;            // 0..63
    const int ac8 = (tid & 3) * 8;

    auto load_stage = [&](int st, int kt) {
        __half* as = Ash + st * ASZ;
        __half* bs = Bsh + st * BSZ;
        if (BM == 128) {
            #pragma unroll
            for (int u = 0; u < 2; ++u) {
                int r = arr + u * 64;
                int m = bm + r;
                bool p = (m < M);
                cpa16h(&as[r * 40 + ac8],
                       A + (size_t)(p ? m : 0) * lda + kt + ac8, p);
            }
        } else {
            int m = bm + arr;
            bool p = (m < M);
            cpa16h(&as[arr * 40 + ac8],
                   A + (size_t)(p ? m : 0) * lda + kt + ac8, p);
        }
        #pragma unroll
        for (int u = 0; u < 2; ++u) {
            int n = arr + u * 64;
            cpa16h(&bs[n * 40 + ac8],
                   BT + (size_t)(bn + n) * ldb + kt + ac8, true);
        }
        asm volatile("cp.async.commit_group;");
    };

    load_stage(0, 0);
    load_stage(1, 32);

    for (int it = 0; it < nIt; ++it) {
        const int cur = it % ST;
        asm volatile("cp.async.wait_group 1;");
        __syncthreads();

        int nx = it + ST - 1;
        if (nx < nIt) load_stage(nx % ST, nx * 32);
        else          asm volatile("cp.async.commit_group;");

        const uint32_t* As2 = (const uint32_t*)(Ash + cur * ASZ);  // stride 20
        const uint32_t* Bs2 = (const uint32_t*)(Bsh + cur * BSZ);
        #pragma unroll
        for (int kk = 0; kk < 2; ++kk) {
            const int cq = (lane & 3) + kk * 8;
            uint32_t af[MI][4];
            #pragma unroll
            for (int mi = 0; mi < MI; ++mi) {
                int r0 = wm * WM + mi * 16 + (lane >> 2);
                af[mi][0] = As2[ r0      * 20 + cq];
                af[mi][1] = As2[(r0 + 8) * 20 + cq];
                af[mi][2] = As2[ r0      * 20 + cq + 4];
                af[mi][3] = As2[(r0 + 8) * 20 + cq + 4];
            }
            uint32_t bf[8][2];
            #pragma unroll
            for (int ni = 0; ni < 8; ++ni) {
                int n = wn * 64 + ni * 8 + (lane >> 2);
                bf[ni][0] = Bs2[n * 20 + cq];
                bf[ni][1] = Bs2[n * 20 + cq + 4];
            }
            #pragma unroll
            for (int mi = 0; mi < MI; ++mi)
                #pragma unroll
                for (int ni = 0; ni < 8; ++ni)
                    mma16(acc[mi][ni], af[mi], bf[ni]);
        }
        __syncthreads();
    }

    #pragma unroll
    for (int mi = 0; mi < MI; ++mi) {
        #pragma unroll
        for (int ni = 0; ni < 8; ++ni) {
            int m0 = bm + wm * WM + mi * 16 + (lane >> 2);
            int n  = bn + wn * 64 + ni * 8 + (lane & 3) * 2;
            float bi0 = bias[n], bi1 = bias[n + 1];
            #pragma unroll
            for (int h = 0; h < 2; ++h) {
                int m = m0 + h * 8;
                if (m < M) {
                    float v0 = acc[mi][ni][h * 2 + 0] + bi0;
                    float v1 = acc[mi][ni][h * 2 + 1] + bi1;
                    if (ACT == 0) {
                        v0 = 0.5f * v0 * (1.f + erff(v0 * 0.70710678118654752f));
                        v1 = 0.5f * v1 * (1.f + erff(v1 * 0.70710678118654752f));
                    } else {
                        v0 = 1.f / (1.f + __expf(-v0));
                        v1 = 1.f / (1.f + __expf(-v1));
                    }
                    if (OUTF == 0) {
                        __half2 hv = __floats2half2_rn(v0, v1);
                        *(__half2*)&((__half*)Cv)[(size_t)m * ldc + coloff + n] = hv;
                    } else {
                        *(float2*)&((float*)Cv)[(size_t)m * ldc + coloff + n] =
                            make_float2(v0, v1);
                    }
                }
            }
        }
    }
}

// ---------------------------------------------------------------------------
// Fused conv head, fp16 MMA for conv2.
// conv2 K remapped: k' = (c*3+ki)*6 + kj', kj'=5 has zero weight -> K'=288.
// h1 stored as duplicated pairs: h1d[row][j] = (h1[row][j], h1[row][j+1]).
// ---------------------------------------------------------------------------
__global__ __launch_bounds__(256)
void conv_head(const float* __restrict__ e,
               const int* __restrict__ idx,
               const float* __restrict__ w1, const float* __restrict__ b1,
               const float* __restrict__ w2, const float* __restrict__ b2,
               const float* __restrict__ Wout, const float* __restrict__ bout,
               float* __restrict__ outp,
               float* __restrict__ flat)
{
    extern __shared__ float sm[];
    float* w1s  = sm;                     // 240
    float* xs   = sm + 240;               // 1040
    float* red  = sm + 1280;              // 16
    float* pool = sm + 1296;              // 8448
    uint32_t* w2h2 = (uint32_t*)(sm + 9744);   // 32 x 145 half2
    uint32_t* h1d  = (uint32_t*)(sm + 14384);  // 33 x 265 half2 (row 32 zero)
    __half* w2h = (__half*)w2h2;
    __half* h1h = (__half*)h1d;

    const int tid = threadIdx.x;
    const int lane = tid & 31, w = tid >> 5;
    const int b = blockIdx.x;

    for (int i = tid; i < 240; i += 256) w1s[i] = w1[i];
    // w2 -> half, layout [o][k'=290 stride], zero where kj'==5 or k'>=288
    for (int i = tid; i < 32 * 290; i += 256) {
        int o = i / 290, k2 = i - o * 290;
        float v = 0.f;
        if (k2 < 288) {
            int c = k2 / 18, rem = k2 - c * 18;
            int ki = rem / 6, kj = rem - ki * 6;
            if (kj < 5) v = w2[o * 240 + c * 15 + ki * 5 + kj];
        }
        w2h[o * 290 + k2] = __float2half_rn(v);
    }
    for (int i = tid; i < 1040; i += 256) xs[i] = 0.f;
    for (int i = tid; i < 33 * 265; i += 256) h1d[i] = 0u;
    __syncthreads();

    const int iv   = idx[b];
    const int r_no = iv / 1512;
    const int p_no = iv - r_no * 1512;
    const float* er = e + (size_t)r_no * DTOT;
    const float* ep = e + (size_t)(NRr + p_no) * DTOT;
    for (int i = tid; i < DTOT; i += 256) {
        xs[2 + i]       = er[i];
        xs[520 + 2 + i] = ep[i];
    }
    __syncthreads();

    // ---- conv1 + leaky + avgpool2 -> h1d (duplicated half pairs) ----
    {
        const int q  = tid;          // pooled col 0..255
        const int j0 = 2 * q;
        const int jc = 2 + q;        // padded col (left pad 2)
        for (int c = 0; c < 16; ++c) {
            float W0[5], W1[5], W2[5];
            #pragma unroll
            for (int kj = 0; kj < 5; ++kj) {
                W0[kj] = w1s[c * 15 + kj];
                W1[kj] = w1s[c * 15 + 5 + kj];
                W2[kj] = w1s[c * 15 + 10 + kj];
            }
            float X0[6], X1[6];
            #pragma unroll
            for (int t = 0; t < 6; ++t) {
                X0[t] = xs[j0 + t];
                X1[t] = xs[520 + j0 + t];
            }
            const float bb = b1[c];
            float v00 = bb, v01 = bb, v10 = bb, v11 = bb;
            float v20 = bb, v21 = bb, v30 = bb, v31 = bb;
            #pragma unroll
            for (int kj = 0; kj < 5; ++kj) {
                v00 = fmaf(W2[kj], X0[kj],     v00);
                v01 = fmaf(W2[kj], X0[kj + 1], v01);
                v10 = fmaf(W1[kj], X0[kj],     v10);
                v10 = fmaf(W2[kj], X1[kj],     v10);
                v11 = fmaf(W1[kj], X0[kj + 1], v11);
                v11 = fmaf(W2[kj], X1[kj + 1], v11);
                v20 = fmaf(W0[kj], X0[kj],     v20);
                v20 = fmaf(W1[kj], X1[kj],     v20);
                v21 = fmaf(W0[kj], X0[kj + 1], v21);
                v21 = fmaf(W1[kj], X1[kj + 1], v21);
                v30 = fmaf(W0[kj], X1[kj],     v30);
                v31 = fmaf(W0[kj], X1[kj + 1], v31);
            }
            float p0 = 0.25f * (lrelu(v00) + lrelu(v01) + lrelu(v10) + lrelu(v11));
            float p1 = 0.25f * (lrelu(v20) + lrelu(v21) + lrelu(v30) + lrelu(v31));
            __half h0 = __float2half_rn(p0);
            __half h1v = __float2half_rn(p1);
            int r0 = (c * 2 + 0) * 530, r1 = (c * 2 + 1) * 530;
            h1h[r0 + 2 * jc]     = h0;   // pair[jc].x
            h1h[r0 + 2 * jc - 1] = h0;   // pair[jc-1].y
            h1h[r1 + 2 * jc]     = h1v;
            h1h[r1 + 2 * jc - 1] = h1v;
        }
    }
    __syncthreads();

    // ---- conv2 via implicit-im2col fp16 MMA (18 k-steps of 16) ----
    float acc[8][4][4];
    #pragma unroll
    for (int nt = 0; nt < 4; ++nt) {
        int o = nt * 8 + 2 * (lane & 3);
        float q0 = b2[o], q1 = b2[o + 1];
        #pragma unroll
        for (int u = 0; u < 8; ++u) {
            acc[u][nt][0] = q0; acc[u][nt][1] = q1;
            acc[u][nt][2] = q0; acc[u][nt][3] = q1;
        }
    }

    const int kq = lane & 3;
    #pragma unroll
    for (int s = 0; s < 18; ++s) {
        const int klo = s * 16 + kq * 2;
        const int khi = klo + 8;
        const int rl0 = klo / 6, ol0 = klo - rl0 * 6;
        const int rl1 = khi / 6, ol1 = khi - rl1 * 6;
        const int c0 = rl0 / 3, ki0 = rl0 - c0 * 3;
        const int c1 = rl1 / 3, ki1 = rl1 - c1 * 3;

        uint32_t bf[4][2];
        #pragma unroll
        for (int nt = 0; nt < 4; ++nt) {
            int n = nt * 8 + (lane >> 2);
            bf[nt][0] = w2h2[n * 145 + s * 8 + kq];
            bf[nt][1] = w2h2[n * 145 + s * 8 + kq + 4];
        }
        #pragma unroll
        for (int u = 0; u < 8; ++u) {
            int i   = u >> 1;
            int col = (((u & 1) ? w + 8 : w) << 4) + (lane >> 2);
            int ra = i + ki0 - 2;
            int row0 = ((unsigned)ra < 2u) ? (c0 * 2 + ra) : 32;
            int rb = i + ki1 - 2;
            int row1 = ((unsigned)rb < 2u) ? (c1 * 2 + rb) : 32;
            uint32_t a[4];
            a[0] = h1d[row0 * 265 + col + ol0];
            a[1] = h1d[row0 * 265 + col + 8 + ol0];
            a[2] = h1d[row1 * 265 + col + ol1];
            a[3] = h1d[row1 * 265 + col + 8 + ol1];
            #pragma unroll
            for (int nt = 0; nt < 4; ++nt)
                mma16(acc[u][nt], a, bf[nt]);
        }
    }

    // ---- lrelu + maxpool (j via shfl, i via regs) + tanh -> pool smem ----
    const bool act = ((lane >> 2) & 1) == 0;
    const int jp = lane >> 3;
    #pragma unroll
    for (int uu = 0; uu < 4; ++uu) {
        int u  = (uu & 1) + (uu >> 1) * 4;     // {0,1,4,5}
        int ip = (u >= 4);
        int jb = (((u & 1) ? w + 8 : w) << 3);
        #pragma unroll
        for (int nt = 0; nt < 4; ++nt) {
            int o = nt * 8 + 2 * (lane & 3);
            float v[4];
            #pragma unroll
            for (int q = 0; q < 4; ++q) {
                float x = lrelu(acc[u][nt][q]);
                float y = lrelu(acc[u + 2][nt][q]);
                x = fmaxf(x, y);
                float z = __shfl_xor_sync(0xffffffffu, x, 4);
                v[q] = fmaxf(x, z);
            }
            if (act) {
                int base  = (ip * 128 + jb + jp) * 33;
                int base2 = base + 4 * 33;
                pool[base  + o]     = tanh_fast(v[0]);
                pool[base  + o + 1] = tanh_fast(v[1]);
                pool[base2 + o]     = tanh_fast(v[2]);
                pool[base2 + o + 1] = tanh_fast(v[3]);
            }
        }
    }
    __syncthreads();

    // ---- coalesced flat write + fused output dot ----
    float d0 = 0.f, d1 = 0.f;
    float* fb = flat + (size_t)b * FLATN;
    const float2* Wo2 = (const float2*)Wout;
    #pragma unroll
    for (int g = 0; g < 32; ++g) {
        float v = pool[tid * 33 + g];
        int k = g * 256 + tid;
        fb[k] = v;
        float2 wv = __ldg(Wo2 + k);
        d0 = fmaf(v, wv.x, d0);
        d1 = fmaf(v, wv.y, d1);
    }
    #pragma unroll
    for (int off = 16; off > 0; off >>= 1) {
        d0 += __shfl_down_sync(0xffffffffu, d0, off);
        d1 += __shfl_down_sync(0xffffffffu, d1, off);
    }
    if (lane == 0) { red[w * 2] = d0; red[w * 2 + 1] = d1; }
    __syncthreads();
    if (tid == 0) {
        float s0 = 0.f, s1 = 0.f;
        #pragma unroll
        for (int i = 0; i < 8; ++i) { s0 += red[i * 2]; s1 += red[i * 2 + 1]; }
        outp[(size_t)b * 2 + 0] = s0 + bout[0];
        outp[(size_t)b * 2 + 1] = s1 + bout[1];
    }
}

// ---------------------------------------------------------------------------
// kernel_launch — att chain on side stream, fun chain + conv on main stream
// ---------------------------------------------------------------------------
extern "C" void kernel_launch(void* const* d_in, const int* in_sizes, int n_in,
                              void* d_out, int out_size)
{
    const float* r_att   = (const float*)d_in[0];
    const float* p_att   = (const float*)d_in[1];
    const float* r_fun   = (const float*)d_in[2];
    const float* p_fun   = (const float*)d_in[3];
    const int*   idx     = (const int*)  d_in[4];
    const float* W_att1  = (const float*)d_in[5];
    const float* b_att1  = (const float*)d_in[6];
    const float* W_att2  = (const float*)d_in[7];
    const float* b_att2  = (const float*)d_in[8];
    const float* W_fun1  = (const float*)d_in[9];
    const float* b_fun1  = (const float*)d_in[10];
    const float* W_fun2  = (const float*)d_in[11];
    const float* b_fun2  = (const float*)d_in[12];
    const float* conv1_w = (const float*)d_in[13];
    const float* conv1_b = (const float*)d_in[14];
    const float* conv2_w = (const float*)d_in[15];
    const float* conv2_b = (const float*)d_in[16];
    const float* W_out   = (const float*)d_in[17];
    const float* b_out   = (const float*)d_in[18];

    float* out  = (float*)d_out;
    float* e    = out;
    float* outp = out + (size_t)NTOT * DTOT;
    float* flat = outp + (size_t)BATCH * 2;

    __half *ahA, *ahF, *wt1a, *wt1f, *wt2a, *wt2f, *hA, *hF;
    cudaGetSymbolAddress((void**)&ahA,  g_ah_att);
    cudaGetSymbolAddress((void**)&ahF,  g_ah_fun);
    cudaGetSymbolAddress((void**)&wt1a, g_wt1a);
    cudaGetSymbolAddress((void**)&wt1f, g_wt1f);
    cudaGetSymbolAddress((void**)&wt2a, g_wt2a);
    cudaGetSymbolAddress((void**)&wt2f, g_wt2f);
    cudaGetSymbolAddress((void**)&hA,   g_h_att);
    cudaGetSymbolAddress((void**)&hF,   g_h_fun);

    static cudaStream_t s_att = nullptr;
    static cudaEvent_t  ev0 = nullptr, evA = nullptr;
    if (!s_att) {
        cudaStreamCreateWithFlags(&s_att, cudaStreamNonBlocking);
        cudaEventCreateWithFlags(&ev0, cudaEventDisableTiming);
        cudaEventCreateWithFlags(&evA, cudaEventDisableTiming);
    }

    const int smG128 = 3 * (128 * 40 + 128 * 40) * 2;   // 61440 B
    const int smG64  = 3 * (64 * 40 + 128 * 40) * 2;    // 46080 B
    cudaFuncSetAttribute(gemm_h<128, 0, 0>,
                         cudaFuncAttributeMaxDynamicSharedMemorySize, smG128);
    cudaFuncSetAttribute(gemm_h<64, 1, 1>,
                         cudaFuncAttributeMaxDynamicSharedMemorySize, smG64);
    const int smC = 23129 * 4;   // 92516 B
    cudaFuncSetAttribute(conv_head,
                         cudaFuncAttributeMaxDynamicSharedMemorySize, smC);

    // fork
    cudaEventRecord(ev0, 0);
    cudaStreamWaitEvent(s_att, ev0, 0);

    // ---- att chain (side stream) ----
    cvtA<<<dim3((KATT_T + 255) / 256, NTOT), 256, 0, s_att>>>(
        r_att, p_att, NRr, KATT, ahA, KATT_T);
    transpose_h<<<dim3(2048 / 32, KATT_T / 32), dim3(32, 8), 0, s_att>>>(
        W_att1, wt1a, KATT, 2048, KATT_T);
    transpose_h<<<dim3(256 / 32, 2048 / 32), dim3(32, 8), 0, s_att>>>(
        W_att2, wt2a, 2048, 256, 2048);
    gemm_h<128, 0, 0><<<dim3(2048 / 128, (NTOT + 127) / 128), 256, smG128, s_att>>>(
        ahA, KATT_T, NTOT, 2048, KATT_T, wt1a, KATT_T, b_att1, hA, 2048, 0);
    gemm_h<64, 1, 1><<<dim3(256 / 128, (NTOT + 63) / 64), 256, smG64, s_att>>>(
        hA, 2048, NTOT, 256, 2048, wt2a, 2048, b_att2, e, DTOT, 0);
    cudaEventRecord(evA, s_att);

    // ---- fun chain (main stream) ----
    cvtA<<<dim3((KFUN_T + 255) / 256, NTOT), 256>>>(
        r_fun, p_fun, NRr, KFUN, ahF, KFUN_T);
    transpose_h<<<dim3(4096 / 32, KFUN_T / 32), dim3(32, 8)>>>(
        W_fun1, wt1f, KFUN, 4096, KFUN_T);
    transpose_h<<<dim3(256 / 32, 4096 / 32), dim3(32, 8)>>>(
        W_fun2, wt2f, 4096, 256, 4096);
    gemm_h<128, 0, 0><<<dim3(4096 / 128, (NTOT + 127) / 128), 256, smG128>>>(
        ahF, KFUN_T, NTOT, 4096, KFUN_T, wt1f, KFUN_T, b_fun1, hF, 4096, 0);
    gemm_h<64, 1, 1><<<dim3(256 / 128, (NTOT + 63) / 64), 256, smG64>>>(
        hF, 4096, NTOT, 256, 4096, wt2f, 4096, b_fun2, e, DTOT, 256);

    // join, then conv head
    cudaStreamWaitEvent(0, evA, 0);
    conv_head<<<BATCH, 256, smC>>>(
        e, idx, conv1_w, conv1_b, conv2_w, conv2_b, W_out, b_out, outp, flat);
}

// round 7
// speedup vs baseline: 5.4080x; 1.1484x over previous
#include <cuda_runtime.h>
#include <cuda_fp16.h>
#include <cstdint>

// ---------------------------------------------------------------------------
// Problem constants
// ---------------------------------------------------------------------------
#define NRr     2000
#define NPp     1512
#define NTOT    3512
#define DTOT    512
#define BATCH   8192
#define FLATN   8192
#define KATT    3000
#define KATT_T  3008
#define KFUN    5603
#define KFUN_T  5632

// Scratch (device globals; allocation is forbidden)
__device__ __half g_ah_att[(size_t)NTOT * KATT_T];
__device__ __half g_ah_fun[(size_t)NTOT * KFUN_T];
__device__ __half g_wt1a [(size_t)2048 * KATT_T];
__device__ __half g_wt1f [(size_t)4096 * KFUN_T];
__device__ __half g_wt2a [(size_t)256 * 2048];
__device__ __half g_wt2f [(size_t)256 * 4096];
__device__ __half g_h_att[(size_t)NTOT * 2048];
__device__ __half g_h_fun[(size_t)NTOT * 4096];

// ---------------------------------------------------------------------------
// helpers
// ---------------------------------------------------------------------------
__device__ __forceinline__ float tanh_fast(float x) {
    float r;
    asm("tanh.approx.f32 %0, %1;" : "=f"(r) : "f"(x));
    return r;
}

__device__ __forceinline__ void mma16(float* d, const uint32_t* a, const uint32_t* b) {
    asm volatile(
        "mma.sync.aligned.m16n8k16.row.col.f32.f16.f16.f32 "
        "{%0,%1,%2,%3},{%4,%5,%6,%7},{%8,%9},{%0,%1,%2,%3};"
        : "+f"(d[0]), "+f"(d[1]), "+f"(d[2]), "+f"(d[3])
        : "r"(a[0]), "r"(a[1]), "r"(a[2]), "r"(a[3]), "r"(b[0]), "r"(b[1]));
}

__device__ __forceinline__ void ldsm4(uint32_t& r0, uint32_t& r1,
                                      uint32_t& r2, uint32_t& r3, uint32_t addr) {
    asm volatile("ldmatrix.sync.aligned.m8n8.x4.shared.b16 {%0,%1,%2,%3}, [%4];"
                 : "=r"(r0), "=r"(r1), "=r"(r2), "=r"(r3) : "r"(addr));
}

__device__ __forceinline__ void cpa16h(__half* smem_dst, const __half* g, bool pred) {
    uint32_t s = (uint32_t)__cvta_generic_to_shared(smem_dst);
    int sz = pred ? 16 : 0;
    asm volatile("cp.async.cg.shared.global [%0], [%1], 16, %2;"
                 :: "r"(s), "l"(g), "r"(sz));
}

__device__ __forceinline__ float lrelu(float v) {
    return v >= 0.f ? v : 0.01f * v;
}

// ---------------------------------------------------------------------------
// Prepass 1: activations fp32 -> half (rows r then p), K zero-padded to KT
// ---------------------------------------------------------------------------
__global__ void cvtA(const float* __restrict__ r, const float* __restrict__ p,
                     int nr, int Kin, __half* __restrict__ dst, int KT)
{
    int row = blockIdx.y;
    int c = blockIdx.x * 256 + threadIdx.x;
    if (c >= KT) return;
    const float* s = (row < nr) ? (r + (size_t)row * Kin)
                                : (p + (size_t)(row - nr) * Kin);
    dst[(size_t)row * KT + c] = (c < Kin) ? __float2half_rn(s[c]) : __half(0.f);
}

// ---------------------------------------------------------------------------
// Prepass 2: W [K][N] fp32 -> WT [N][KT] half (zero for k >= K). N % 32 == 0.
// ---------------------------------------------------------------------------
__global__ void transpose_h(const float* __restrict__ W, __half* __restrict__ WT,
                            int K, int N, int KT)
{
    __shared__ float t[32][33];
    int k0 = blockIdx.y * 32, n0 = blockIdx.x * 32;
    #pragma unroll
    for (int r = threadIdx.y; r < 32; r += 8) {
        int k = k0 + r;
        t[r][threadIdx.x] = (k < K) ? W[(size_t)k * N + n0 + threadIdx.x] : 0.f;
    }
    __syncthreads();
    #pragma unroll
    for (int r = threadIdx.y; r < 32; r += 8) {
        int n = n0 + r, k = k0 + threadIdx.x;
        WT[(size_t)n * KT + k] = __float2half_rn(t[threadIdx.x][r]);
    }
}

// ---------------------------------------------------------------------------
// FP16 GEMM (m16n8k16) with ldmatrix fragments, 3-stage cp.async pipeline.
// C[m, coloff+n] = act(sum_k A[m,k]*BT[n,k] + bias[n])
// ---------------------------------------------------------------------------
template<int BM, int ACT, int OUTF>
__global__ __launch_bounds__(256, 2)
void gemm_h(const __half* __restrict__ A, int lda, int M, int N, int KT,
            const __half* __restrict__ BT, int ldb,
            const float* __restrict__ bias,
            void* __restrict__ Cv, int ldc, int coloff)
{
    constexpr int ST = 3;
    constexpr int WM = BM / 4;
    constexpr int MI = WM / 16;
    constexpr int ASZ = BM * 40;     // halves
    constexpr int BSZ = 128 * 40;    // halves

    extern __shared__ __half hsm[];
    __half* Ash = hsm;
    __half* Bsh = hsm + ST * ASZ;

    const int tid  = threadIdx.x;
    const int lane = tid & 31, warp = tid >> 5;
    const int wm = warp >> 1, wn = warp & 1;
    const int bm = blockIdx.y * BM, bn = blockIdx.x * 128;

    float acc[MI][8][4];
    #pragma unroll
    for (int i = 0; i < MI; ++i)
        #pragma unroll
        for (int j = 0; j < 8; ++j)
            #pragma unroll
            for (int q = 0; q < 4; ++q) acc[i][j][q] = 0.f;

    const int nIt = KT / 32;
    const int arr = tid >> 2;
    const int ac8 = (tid & 3) * 8;

    // ldmatrix per-lane mappings
    const int lmA_row  = lane & 15;            // A: row within 16-row tile
    const int lmA_koff = (lane >> 4) * 8;      // A: k offset 0/8
    const int lmB_n    = (lane & 7) + ((lane >> 4) & 1) * 8;
    const int lmB_koff = ((lane >> 3) & 1) * 8;

    const uint32_t ash0 = (uint32_t)__cvta_generic_to_shared(Ash);
    const uint32_t bsh0 = (uint32_t)__cvta_generic_to_shared(Bsh);

    auto load_stage = [&](int st, int kt) {
        __half* as = Ash + st * ASZ;
        __half* bs = Bsh + st * BSZ;
        if (BM == 128) {
            #pragma unroll
            for (int u = 0; u < 2; ++u) {
                int r = arr + u * 64;
                int m = bm + r;
                bool p = (m < M);
                cpa16h(&as[r * 40 + ac8],
                       A + (size_t)(p ? m : 0) * lda + kt + ac8, p);
            }
        } else {
            int m = bm + arr;
            bool p = (m < M);
            cpa16h(&as[arr * 40 + ac8],
                   A + (size_t)(p ? m : 0) * lda + kt + ac8, p);
        }
        #pragma unroll
        for (int u = 0; u < 2; ++u) {
            int n = arr + u * 64;
            cpa16h(&bs[n * 40 + ac8],
                   BT + (size_t)(bn + n) * ldb + kt + ac8, true);
        }
        asm volatile("cp.async.commit_group;");
    };

    load_stage(0, 0);
    load_stage(1, 32);

    for (int it = 0; it < nIt; ++it) {
        const int cur = it % ST;
        asm volatile("cp.async.wait_group 1;");
        __syncthreads();

        int nx = it + ST - 1;
        if (nx < nIt) load_stage(nx % ST, nx * 32);
        else          asm volatile("cp.async.commit_group;");

        const uint32_t asb = ash0 + cur * ASZ * 2;
        const uint32_t bsb = bsh0 + cur * BSZ * 2;
        #pragma unroll
        for (int kk = 0; kk < 2; ++kk) {
            uint32_t af[MI][4];
            #pragma unroll
            for (int mi = 0; mi < MI; ++mi) {
                int r0 = wm * WM + mi * 16;
                uint32_t addr = asb +
                    (uint32_t)(((r0 + lmA_row) * 40 + lmA_koff + kk * 16) * 2);
                ldsm4(af[mi][0], af[mi][1], af[mi][2], af[mi][3], addr);
            }
            uint32_t bf[8][2];
            #pragma unroll
            for (int np = 0; np < 4; ++np) {
                int n0 = wn * 64 + np * 16;
                uint32_t addr = bsb +
                    (uint32_t)(((n0 + lmB_n) * 40 + lmB_koff + kk * 16) * 2);
                ldsm4(bf[2 * np][0], bf[2 * np][1],
                      bf[2 * np + 1][0], bf[2 * np + 1][1], addr);
            }
            #pragma unroll
            for (int mi = 0; mi < MI; ++mi)
                #pragma unroll
                for (int ni = 0; ni < 8; ++ni)
                    mma16(acc[mi][ni], af[mi], bf[ni]);
        }
        __syncthreads();
    }

    #pragma unroll
    for (int mi = 0; mi < MI; ++mi) {
        #pragma unroll
        for (int ni = 0; ni < 8; ++ni) {
            int m0 = bm + wm * WM + mi * 16 + (lane >> 2);
            int n  = bn + wn * 64 + ni * 8 + (lane & 3) * 2;
            float bi0 = bias[n], bi1 = bias[n + 1];
            #pragma unroll
            for (int h = 0; h < 2; ++h) {
                int m = m0 + h * 8;
                if (m < M) {
                    float v0 = acc[mi][ni][h * 2 + 0] + bi0;
                    float v1 = acc[mi][ni][h * 2 + 1] + bi1;
                    if (ACT == 0) {
                        v0 = 0.5f * v0 * (1.f + erff(v0 * 0.70710678118654752f));
                        v1 = 0.5f * v1 * (1.f + erff(v1 * 0.70710678118654752f));
                    } else {
                        v0 = 1.f / (1.f + __expf(-v0));
                        v1 = 1.f / (1.f + __expf(-v1));
                    }
                    if (OUTF == 0) {
                        __half2 hv = __floats2half2_rn(v0, v1);
                        *(__half2*)&((__half*)Cv)[(size_t)m * ldc + coloff + n] = hv;
                    } else {
                        *(float2*)&((float*)Cv)[(size_t)m * ldc + coloff + n] =
                            make_float2(v0, v1);
                    }
                }
            }
        }
    }
}

// ---------------------------------------------------------------------------
// Fused conv head. conv2 K reordered as ki*96 + c*6 + kj (kj=5 zero pad),
// and only valid (u, ki) combinations are computed (halves the MMA work).
// ---------------------------------------------------------------------------
__global__ __launch_bounds__(256)
void conv_head(const float* __restrict__ e,
               const int* __restrict__ idx,
               const float* __restrict__ w1, const float* __restrict__ b1,
               const float* __restrict__ w2, const float* __restrict__ b2,
               const float* __restrict__ Wout, const float* __restrict__ bout,
               float* __restrict__ outp,
               float* __restrict__ flat)
{
    extern __shared__ float sm[];
    float* w1s  = sm;                          // 240
    float* xs   = sm + 240;                    // 1040
    float* red  = sm + 1280;                   // 16
    float* pool = sm + 1296;                   // 8448
    uint32_t* w2h2 = (uint32_t*)(sm + 9744);   // 32 x 148 half2
    uint32_t* h1d  = (uint32_t*)(sm + 14480);  // 33 x 265 half2
    __half* w2h = (__half*)w2h2;
    __half* h1h = (__half*)h1d;

    const int tid = threadIdx.x;
    const int lane = tid & 31, w = tid >> 5;
    const int b = blockIdx.x;

    for (int i = tid; i < 240; i += 256) w1s[i] = w1[i];
    // w2 -> half, layout [o][k'], k' = ki*96 + c*6 + kj (kj=5 -> 0), stride 296
    for (int i = tid; i < 32 * 296; i += 256) {
        int o = i / 296, k2 = i - o * 296;
        float v = 0.f;
        if (k2 < 288) {
            int ki = k2 / 96, rem = k2 - ki * 96;
            int c = rem / 6, kj = rem - c * 6;
            if (kj < 5) v = w2[o * 240 + c * 15 + ki * 5 + kj];
        }
        w2h[o * 296 + k2] = __float2half_rn(v);
    }
    for (int i = tid; i < 1040; i += 256) xs[i] = 0.f;
    for (int i = tid; i < 33 * 265; i += 256) h1d[i] = 0u;
    __syncthreads();

    const int iv   = idx[b];
    const int r_no = iv / 1512;
    const int p_no = iv - r_no * 1512;
    const float* er = e + (size_t)r_no * DTOT;
    const float* ep = e + (size_t)(NRr + p_no) * DTOT;
    for (int i = tid; i < DTOT; i += 256) {
        xs[2 + i]       = er[i];
        xs[520 + 2 + i] = ep[i];
    }
    __syncthreads();

    // ---- conv1 + leaky + avgpool2 -> h1d (duplicated half pairs) ----
    {
        const int q  = tid;
        const int j0 = 2 * q;
        const int jc = 2 + q;
        for (int c = 0; c < 16; ++c) {
            float W0[5], W1[5], W2[5];
            #pragma unroll
            for (int kj = 0; kj < 5; ++kj) {
                W0[kj] = w1s[c * 15 + kj];
                W1[kj] = w1s[c * 15 + 5 + kj];
                W2[kj] = w1s[c * 15 + 10 + kj];
            }
            float X0[6], X1[6];
            #pragma unroll
            for (int t = 0; t < 6; ++t) {
                X0[t] = xs[j0 + t];
                X1[t] = xs[520 + j0 + t];
            }
            const float bb = b1[c];
            float v00 = bb, v01 = bb, v10 = bb, v11 = bb;
            float v20 = bb, v21 = bb, v30 = bb, v31 = bb;
            #pragma unroll
            for (int kj = 0; kj < 5; ++kj) {
                v00 = fmaf(W2[kj], X0[kj],     v00);
                v01 = fmaf(W2[kj], X0[kj + 1], v01);
                v10 = fmaf(W1[kj], X0[kj],     v10);
                v10 = fmaf(W2[kj], X1[kj],     v10);
                v11 = fmaf(W1[kj], X0[kj + 1], v11);
                v11 = fmaf(W2[kj], X1[kj + 1], v11);
                v20 = fmaf(W0[kj], X0[kj],     v20);
                v20 = fmaf(W1[kj], X1[kj],     v20);
                v21 = fmaf(W0[kj], X0[kj + 1], v21);
                v21 = fmaf(W1[kj], X1[kj + 1], v21);
                v30 = fmaf(W0[kj], X1[kj],     v30);
                v31 = fmaf(W0[kj], X1[kj + 1], v31);
            }
            float p0 = 0.25f * (lrelu(v00) + lrelu(v01) + lrelu(v10) + lrelu(v11));
            float p1 = 0.25f * (lrelu(v20) + lrelu(v21) + lrelu(v30) + lrelu(v31));
            __half h0 = __float2half_rn(p0);
            __half h1v = __float2half_rn(p1);
            int r0 = (c * 2 + 0) * 530, r1 = (c * 2 + 1) * 530;
            h1h[r0 + 2 * jc]     = h0;
            h1h[r0 + 2 * jc - 1] = h0;
            h1h[r1 + 2 * jc]     = h1v;
            h1h[r1 + 2 * jc - 1] = h1v;
        }
    }
    __syncthreads();

    // ---- conv2: valid-ki-only implicit-im2col fp16 MMA ----
    float acc[8][4][4];
    #pragma unroll
    for (int nt = 0; nt < 4; ++nt) {
        int o = nt * 8 + 2 * (lane & 3);
        float q0 = b2[o], q1 = b2[o + 1];
        #pragma unroll
        for (int u = 0; u < 8; ++u) {
            acc[u][nt][0] = q0; acc[u][nt][1] = q1;
            acc[u][nt][2] = q0; acc[u][nt][3] = q1;
        }
    }

    const int kq = lane & 3;
    const int col_lo = (w << 4) + (lane >> 2);
    const int col_hi = ((w + 8) << 4) + (lane >> 2);

    #pragma unroll
    for (int ki = 0; ki < 3; ++ki) {
        const int u0 = (2 - ki) * 2;   // ki=0 -> u 4..7, ki=1 -> 2..5, ki=2 -> 0..3
        #pragma unroll
        for (int s = 0; s < 6; ++s) {
            const int klo = s * 16 + kq * 2;   // even, within 96-block
            const int khi = klo + 8;
            const int c0 = klo / 6, ol0 = klo - c0 * 6;
            const int c1 = khi / 6, ol1 = khi - c1 * 6;
            const int kb = ki * 48 + s * 8 + kq;    // half2 index in w2 row

            uint32_t bf[4][2];
            #pragma unroll
            for (int nt = 0; nt < 4; ++nt) {
                int n = nt * 8 + (lane >> 2);
                bf[nt][0] = w2h2[n * 148 + kb];
                bf[nt][1] = w2h2[n * 148 + kb + 4];
            }
            #pragma unroll
            for (int v = 0; v < 4; ++v) {
                const int u = u0 + v;
                const int r = v >> 1;           // {0,0,1,1}
                const int row0 = c0 * 2 + r;
                const int row1 = c1 * 2 + r;
                const int col = (u & 1) ? col_hi : col_lo;
                uint32_t a[4];
                a[0] = h1d[row0 * 265 + col + ol0];
                a[1] = h1d[row0 * 265 + col + 8 + ol0];
                a[2] = h1d[row1 * 265 + col + ol1];
                a[3] = h1d[row1 * 265 + col + 8 + ol1];
                #pragma unroll
                for (int nt = 0; nt < 4; ++nt)
                    mma16(acc[u][nt], a, bf[nt]);
            }
        }
    }

    // ---- lrelu + maxpool (j via shfl, i via regs) + tanh -> pool smem ----
    const bool act = ((lane >> 2) & 1) == 0;
    const int jp = lane >> 3;
    #pragma unroll
    for (int uu = 0; uu < 4; ++uu) {
        int u  = (uu & 1) + (uu >> 1) * 4;     // {0,1,4,5}
        int ip = (u >= 4);
        int jb = (((u & 1) ? w + 8 : w) << 3);
        #pragma unroll
        for (int nt = 0; nt < 4; ++nt) {
            int o = nt * 8 + 2 * (lane & 3);
            float v[4];
            #pragma unroll
            for (int q = 0; q < 4; ++q) {
                float x = lrelu(acc[u][nt][q]);
                float y = lrelu(acc[u + 2][nt][q]);
                x = fmaxf(x, y);
                float z = __shfl_xor_sync(0xffffffffu, x, 4);
                v[q] = fmaxf(x, z);
            }
            if (act) {
                int base  = (ip * 128 + jb + jp) * 33;
                int base2 = base + 4 * 33;
                pool[base  + o]     = tanh_fast(v[0]);
                pool[base  + o + 1] = tanh_fast(v[1]);
                pool[base2 + o]     = tanh_fast(v[2]);
                pool[base2 + o + 1] = tanh_fast(v[3]);
            }
        }
    }
    __syncthreads();

    // ---- coalesced flat write + fused output dot ----
    float d0 = 0.f, d1 = 0.f;
    float* fb = flat + (size_t)b * FLATN;
    const float2* Wo2 = (const float2*)Wout;
    #pragma unroll
    for (int g = 0; g < 32; ++g) {
        float v = pool[tid * 33 + g];
        int k = g * 256 + tid;
        fb[k] = v;
        float2 wv = __ldg(Wo2 + k);
        d0 = fmaf(v, wv.x, d0);
        d1 = fmaf(v, wv.y, d1);
    }
    #pragma unroll
    for (int off = 16; off > 0; off >>= 1) {
        d0 += __shfl_down_sync(0xffffffffu, d0, off);
        d1 += __shfl_down_sync(0xffffffffu, d1, off);
    }
    if (lane == 0) { red[w * 2] = d0; red[w * 2 + 1] = d1; }
    __syncthreads();
    if (tid == 0) {
        float s0 = 0.f, s1 = 0.f;
        #pragma unroll
        for (int i = 0; i < 8; ++i) { s0 += red[i * 2]; s1 += red[i * 2 + 1]; }
        outp[(size_t)b * 2 + 0] = s0 + bout[0];
        outp[(size_t)b * 2 + 1] = s1 + bout[1];
    }
}

// ---------------------------------------------------------------------------
// kernel_launch — att chain on side stream, fun chain + conv on main stream
// ---------------------------------------------------------------------------
extern "C" void kernel_launch(void* const* d_in, const int* in_sizes, int n_in,
                              void* d_out, int out_size)
{
    const float* r_att   = (const float*)d_in[0];
    const float* p_att   = (const float*)d_in[1];
    const float* r_fun   = (const float*)d_in[2];
    const float* p_fun   = (const float*)d_in[3];
    const int*   idx     = (const int*)  d_in[4];
    const float* W_att1  = (const float*)d_in[5];
    const float* b_att1  = (const float*)d_in[6];
    const float* W_att2  = (const float*)d_in[7];
    const float* b_att2  = (const float*)d_in[8];
    const float* W_fun1  = (const float*)d_in[9];
    const float* b_fun1  = (const float*)d_in[10];
    const float* W_fun2  = (const float*)d_in[11];
    const float* b_fun2  = (const float*)d_in[12];
    const float* conv1_w = (const float*)d_in[13];
    const float* conv1_b = (const float*)d_in[14];
    const float* conv2_w = (const float*)d_in[15];
    const float* conv2_b = (const float*)d_in[16];
    const float* W_out   = (const float*)d_in[17];
    const float* b_out   = (const float*)d_in[18];

    float* out  = (float*)d_out;
    float* e    = out;
    float* outp = out + (size_t)NTOT * DTOT;
    float* flat = outp + (size_t)BATCH * 2;

    __half *ahA, *ahF, *wt1a, *wt1f, *wt2a, *wt2f, *hA, *hF;
    cudaGetSymbolAddress((void**)&ahA,  g_ah_att);
    cudaGetSymbolAddress((void**)&ahF,  g_ah_fun);
    cudaGetSymbolAddress((void**)&wt1a, g_wt1a);
    cudaGetSymbolAddress((void**)&wt1f, g_wt1f);
    cudaGetSymbolAddress((void**)&wt2a, g_wt2a);
    cudaGetSymbolAddress((void**)&wt2f, g_wt2f);
    cudaGetSymbolAddress((void**)&hA,   g_h_att);
    cudaGetSymbolAddress((void**)&hF,   g_h_fun);

    static cudaStream_t s_att = nullptr;
    static cudaEvent_t  ev0 = nullptr, evA = nullptr;
    if (!s_att) {
        cudaStreamCreateWithFlags(&s_att, cudaStreamNonBlocking);
        cudaEventCreateWithFlags(&ev0, cudaEventDisableTiming);
        cudaEventCreateWithFlags(&evA, cudaEventDisableTiming);
    }

    const int smG128 = 3 * (128 * 40 + 128 * 40) * 2;   // 61440 B
    const int smG64  = 3 * (64 * 40 + 128 * 40) * 2;    // 46080 B
    cudaFuncSetAttribute(gemm_h<128, 0, 0>,
                         cudaFuncAttributeMaxDynamicSharedMemorySize, smG128);
    cudaFuncSetAttribute(gemm_h<64, 1, 1>,
                         cudaFuncAttributeMaxDynamicSharedMemorySize, smG64);
    const int smC = (9744 + 4736 + 8745) * 4;           // 93,  92900 B
    cudaFuncSetAttribute(conv_head,
                         cudaFuncAttributeMaxDynamicSharedMemorySize, smC);

    // fork
    cudaEventRecord(ev0, 0);
    cudaStreamWaitEvent(s_att, ev0, 0);

    // ---- att chain (side stream) ----
    cvtA<<<dim3((KATT_T + 255) / 256, NTOT), 256, 0, s_att>>>(
        r_att, p_att, NRr, KATT, ahA, KATT_T);
    transpose_h<<<dim3(2048 / 32, KATT_T / 32), dim3(32, 8), 0, s_att>>>(
        W_att1, wt1a, KATT, 2048, KATT_T);
    transpose_h<<<dim3(256 / 32, 2048 / 32), dim3(32, 8), 0, s_att>>>(
        W_att2, wt2a, 2048, 256, 2048);
    gemm_h<128, 0, 0><<<dim3(2048 / 128, (NTOT + 127) / 128), 256, smG128, s_att>>>(
        ahA, KATT_T, NTOT, 2048, KATT_T, wt1a, KATT_T, b_att1, hA, 2048, 0);
    gemm_h<64, 1, 1><<<dim3(256 / 128, (NTOT + 63) / 64), 256, smG64, s_att>>>(
        hA, 2048, NTOT, 256, 2048, wt2a, 2048, b_att2, e, DTOT, 0);
    cudaEventRecord(evA, s_att);

    // ---- fun chain (main stream) ----
    cvtA<<<dim3((KFUN_T + 255) / 256, NTOT), 256>>>(
        r_fun, p_fun, NRr, KFUN, ahF, KFUN_T);
    transpose_h<<<dim3(4096 / 32, KFUN_T / 32), dim3(32, 8)>>>(
        W_fun1, wt1f, KFUN, 4096, KFUN_T);
    transpose_h<<<dim3(256 / 32, 4096 / 32), dim3(32, 8)>>>(
        W_fun2, wt2f, 4096, 256, 4096);
    gemm_h<128, 0, 0><<<dim3(4096 / 128, (NTOT + 127) / 128), 256, smG128>>>(
        ahF, KFUN_T, NTOT, 4096, KFUN_T, wt1f, KFUN_T, b_fun1, hF, 4096, 0);
    gemm_h<64, 1, 1><<<dim3(256 / 128, (NTOT + 63) / 64), 256, smG64>>>(
        hF, 4096, NTOT, 256, 4096, wt2f, 4096, b_fun2, e, DTOT, 256);

    // join, then conv head
    cudaStreamWaitEvent(0, evA, 0);
    conv_head<<<BATCH, 256, smC>>>(
        e, idx, conv1_w, conv1_b, conv2_w, conv2_b, W_out, b_out, outp, flat);
}